// round 3
// baseline (speedup 1.0000x reference)
#include <cuda_runtime.h>
#include <math.h>
#include <stdint.h>

// ---------------- problem constants ----------------
#define BATCH  16384
#define NNUM   16
#define NCAT   24
#define KCLS   16
#define CATDIM 384          // NCAT*KCLS
#define DIN    400          // NNUM + CATDIM
#define DIMT   1024
#define HIDN   1024
#define TSTEPS 1000

#define LOGK_F 2.772588722239781f      // log(16) rounded to fp32
#define CL_F   (-69.07755278982137f)   // log(1e-30) in fp32

// ---------------- device scratch (static: no allocs allowed) ----------------
__device__ float d_LOG_A[TSTEPS], d_LOG_1M_A[TSTEPS];
__device__ float d_LOG_CA[TSTEPS], d_LOG_1M_CA[TSTEPS];
__device__ float d_SQAC[TSTEPS], d_SQ1MAC[TSTEPS];
__device__ float d_KLP;                 // kl_prior per row (constant)
__device__ int   d_t64, d_c64;          // dtype sniff flags
__device__ int   d_TT[BATCH];
__device__ int   d_CAT[BATCH * NCAT];
__device__ int   d_SAMP[BATCH * NCAT];
__device__ float d_E0[TSTEPS * DIMT];
__device__ float d_E1[TSTEPS * DIMT];
__device__ float d_EMB[TSTEPS * DIMT];
__device__ float d_SUMALL[DIMT];        // sum of the 384 categorical proj_w rows
__device__ float d_H[(size_t)BATCH * DIMT];
__device__ float d_U[(size_t)BATCH * HIDN];
__device__ float d_OUT[(size_t)BATCH * DIN];
__device__ float d_PART[BATCH / 8];

// ---------------- helpers ----------------
__device__ __forceinline__ float laddexp(float a, float b) {
    float m = fmaxf(a, b);
    return m + logf(expf(a - m) + expf(b - m));
}

// ---------------- schedules (fp64 to match numpy, then cast) ----------------
__global__ void sched_kernel() {
    if (threadIdx.x != 0) return;
    const double PI = 3.14159265358979323846;
    double lca = 0.0;
    for (int i = 0; i < TSTEPS; i++) {
        double u0 = (double)i / (double)TSTEPS;
        double u1 = (double)(i + 1) / (double)TSTEPS;
        double c0 = cos((u0 + 0.008) / 1.008 * PI / 2.0); double ab0 = c0 * c0;
        double c1 = cos((u1 + 0.008) / 1.008 * PI / 2.0); double ab1 = c1 * c1;
        double beta = 1.0 - ab1 / ab0;
        if (beta > 0.999) beta = 0.999;
        double la = log(1.0 - beta);
        lca += la;
        d_LOG_A[i]     = (float)la;
        d_LOG_1M_A[i]  = (float)log(1.0 - exp(la) + 1e-40);
        d_LOG_CA[i]    = (float)lca;
        d_LOG_1M_CA[i] = (float)log(1.0 - exp(lca) + 1e-40);
        double ac = exp(lca);
        d_SQAC[i]   = (float)sqrt(ac);
        d_SQ1MAC[i] = (float)sqrt(1.0 - ac);
    }
    // kl_prior: same for every row (depends only on one-hot structure at t=T-1)
    float hT = laddexp(d_LOG_CA[TSTEPS - 1], d_LOG_1M_CA[TSTEPS - 1] - LOGK_F);
    float oT = laddexp(CL_F + d_LOG_CA[TSTEPS - 1], d_LOG_1M_CA[TSTEPS - 1] - LOGK_F);
    d_KLP = (float)NCAT * (expf(hT) * (hT + LOGK_F) + 15.0f * expf(oT) * (oT + LOGK_F));
}

// ---------------- int64 vs int32 sniff + conversion ----------------
__global__ void detect_kernel(const int* __restrict__ traw, const int* __restrict__ craw) {
    if (threadIdx.x != 0) return;
    int z = 1;
    for (int i = 0; i < 64; i++) if (traw[2 * i + 1] != 0) { z = 0; break; }
    d_t64 = z;
    z = 1;
    for (int i = 0; i < 64; i++) if (craw[2 * i + 1] != 0) { z = 0; break; }
    d_c64 = z;
}
__global__ void convert_t_kernel(const int* __restrict__ raw) {
    int i = blockIdx.x * blockDim.x + threadIdx.x;
    if (i < BATCH) d_TT[i] = d_t64 ? raw[2 * i] : raw[i];
}
__global__ void convert_cat_kernel(const int* __restrict__ raw) {
    int i = blockIdx.x * blockDim.x + threadIdx.x;
    if (i < BATCH * NCAT) d_CAT[i] = d_c64 ? raw[2 * i] : raw[i];
}

// ---------------- timestep embedding for all 1000 unique t ----------------
__global__ void temb_kernel() {
    int t = blockIdx.x;
    int j = blockIdx.y * blockDim.x + threadIdx.x;   // 0..1023
    int h = j & 511;
    float freq = expf(-9.210340371976184f * (float)h / 512.0f);
    float arg = (float)t * freq;
    d_E0[t * DIMT + j] = (j < 512) ? cosf(arg) : sinf(arg);
}

// ---------------- SGEMM: C = epi(A@B + bias), row-major ----------------
#define BM 128
#define BN 128
#define BK 8
#define TM 8
#define TN 8
__global__ __launch_bounds__(256) void sgemm_kernel(
    const float* __restrict__ A, const float* __restrict__ B,
    const float* __restrict__ bias, float* __restrict__ C,
    int M, int N, int K, int epi)
{
    __shared__ float As[BK][BM];
    __shared__ float Bs[BK][BN];
    int tid = threadIdx.x;
    int rowBase = blockIdx.y * BM;
    int colBase = blockIdx.x * BN;

    int aRow = tid >> 1;            // 0..127
    int aCol = (tid & 1) * 4;       // 0 or 4
    int bRow = tid >> 5;            // 0..7
    int bCol = (tid & 31) * 4;      // 0..124

    int tRow = (tid >> 4) * TM;
    int tCol = (tid & 15) * TN;

    float acc[TM][TN] = {};
    float ar[TM], br[TN];

    for (int k0 = 0; k0 < K; k0 += BK) {
        // load A tile (transposed into smem)
        {
            int gr = rowBase + aRow;
            float4 v = make_float4(0.f, 0.f, 0.f, 0.f);
            if (gr < M) v = *reinterpret_cast<const float4*>(&A[(size_t)gr * K + k0 + aCol]);
            As[aCol + 0][aRow] = v.x;
            As[aCol + 1][aRow] = v.y;
            As[aCol + 2][aRow] = v.z;
            As[aCol + 3][aRow] = v.w;
        }
        // load B tile
        {
            int gc = colBase + bCol;
            float4 v = make_float4(0.f, 0.f, 0.f, 0.f);
            if (gc + 3 < N) {
                v = *reinterpret_cast<const float4*>(&B[(size_t)(k0 + bRow) * N + gc]);
            } else if (gc < N) {
                float tmp[4] = {0.f, 0.f, 0.f, 0.f};
                for (int e = 0; e < 4; e++) if (gc + e < N) tmp[e] = B[(size_t)(k0 + bRow) * N + gc + e];
                v = make_float4(tmp[0], tmp[1], tmp[2], tmp[3]);
            }
            *reinterpret_cast<float4*>(&Bs[bRow][bCol]) = v;
        }
        __syncthreads();
        #pragma unroll
        for (int kk = 0; kk < BK; kk++) {
            #pragma unroll
            for (int i = 0; i < TM; i++) ar[i] = As[kk][tRow + i];
            #pragma unroll
            for (int j = 0; j < TN; j++) br[j] = Bs[kk][tCol + j];
            #pragma unroll
            for (int i = 0; i < TM; i++)
                #pragma unroll
                for (int j = 0; j < TN; j++)
                    acc[i][j] += ar[i] * br[j];
        }
        __syncthreads();
    }

    #pragma unroll
    for (int i = 0; i < TM; i++) {
        int gr = rowBase + tRow + i;
        if (gr >= M) continue;
        #pragma unroll
        for (int j = 0; j < TN; j++) {
            int gc = colBase + tCol + j;
            if (gc >= N) continue;
            float v = acc[i][j] + bias[gc];
            if (epi == 1) v = fmaxf(v, 0.f);                       // relu
            else if (epi == 2) v = v / (1.f + expf(-v));           // silu
            C[(size_t)gr * N + gc] = v;
        }
    }
}

// ---------------- sum of categorical proj_w rows ----------------
__global__ void sumall_kernel(const float* __restrict__ proj_w) {
    int j = blockIdx.x * blockDim.x + threadIdx.x;
    if (j >= DIMT) return;
    float s = 0.f;
    for (int r = NNUM; r < DIN; r++) s += proj_w[(size_t)r * DIMT + j];
    d_SUMALL[j] = s;
}

// ---------------- build h = x_in@proj_w + proj_b + emb (one block per row) ----
__global__ __launch_bounds__(256) void build_h_kernel(
    const float* __restrict__ x_num, const float* __restrict__ noise,
    const float* __restrict__ gumbel, const float* __restrict__ proj_w,
    const float* __restrict__ proj_b)
{
    int b = blockIdx.x;
    int tid = threadIdx.x;
    __shared__ float s_xnt[NNUM];
    __shared__ int   s_samp[NCAT];
    int t = d_TT[b];

    if (tid < NNUM)
        s_xnt[tid] = d_SQAC[t] * x_num[b * NNUM + tid] + d_SQ1MAC[t] * noise[b * NNUM + tid];

    if (tid < NCAT) {
        int hot = d_CAT[b * NCAT + tid];
        float hv = laddexp(d_LOG_CA[t], d_LOG_1M_CA[t] - LOGK_F);
        float ov = laddexp(CL_F + d_LOG_CA[t], d_LOG_1M_CA[t] - LOGK_F);
        const float* gp = gumbel + (size_t)b * CATDIM + tid * KCLS;
        float best = -1e30f; int bi = 0;
        #pragma unroll
        for (int k = 0; k < KCLS; k++) {
            float g = -logf(-logf(gp[k] + 1e-30f) + 1e-30f);
            float v = g + ((k == hot) ? hv : ov);
            if (v > best) { best = v; bi = k; }
        }
        s_samp[tid] = bi;
        d_SAMP[b * NCAT + tid] = bi;
    }
    __syncthreads();

    #pragma unroll
    for (int r = 0; r < DIMT / 256; r++) {
        int j = tid + 256 * r;
        float acc = d_EMB[t * DIMT + j] + proj_b[j] + CL_F * d_SUMALL[j];
        #pragma unroll
        for (int i = 0; i < NNUM; i++) acc += s_xnt[i] * proj_w[i * DIMT + j];
        #pragma unroll
        for (int c = 0; c < NCAT; c++)
            acc -= CL_F * proj_w[(size_t)(NNUM + c * KCLS + s_samp[c]) * DIMT + j];
        d_H[(size_t)b * DIMT + j] = acc;
    }
}

// ---------------- per-row loss (1 warp per row, 8 rows per block) ----------
__global__ __launch_bounds__(256) void loss_kernel(const float* __restrict__ noise) {
    int warp = threadIdx.x >> 5, lane = threadIdx.x & 31;
    int b = blockIdx.x * 8 + warp;
    __shared__ float s_row[8];
    int t = d_TT[b];
    int tm1 = (t > 0) ? t - 1 : 0;
    const float* outp = d_OUT + (size_t)b * DIN;

    float g = 0.f;
    if (lane < NNUM) { float d = noise[b * NNUM + lane] - outp[lane]; g = d * d; }

    float kl = 0.f, dec = 0.f;
    if (lane < NCAT) {
        int hot = d_CAT[b * NCAT + lane];
        int sm  = d_SAMP[b * NCAT + lane];
        const float* oc = outp + NNUM + lane * KCLS;
        float v[KCLS];
        float mx = -1e30f;
        #pragma unroll
        for (int k = 0; k < KCLS; k++) { v[k] = oc[k]; mx = fmaxf(mx, v[k]); }
        float se = 0.f;
        #pragma unroll
        for (int k = 0; k < KCLS; k++) se += expf(v[k] - mx);
        float lse = mx + logf(se);

        float PH = laddexp(d_LOG_A[t], d_LOG_1M_A[t] - LOGK_F);
        float PO = laddexp(CL_F + d_LOG_A[t], d_LOG_1M_A[t] - LOGK_F);
        float H1, O1;
        if (t == 0) { H1 = 0.f; O1 = CL_F; }
        else {
            H1 = laddexp(d_LOG_CA[tm1], d_LOG_1M_CA[tm1] - LOGK_F);
            O1 = laddexp(CL_F + d_LOG_CA[tm1], d_LOG_1M_CA[tm1] - LOGK_F);
        }

        float unm[KCLS], unt[KCLS];
        float mmax = -1e30f, tmax = -1e30f;
        #pragma unroll
        for (int k = 0; k < KCLS; k++) {
            float lx0 = v[k] - lse;
            float ev  = (t == 0) ? lx0
                                 : laddexp(lx0 + d_LOG_CA[tm1], d_LOG_1M_CA[tm1] - LOGK_F);
            float pk  = (k == sm) ? PH : PO;
            float um = ev + pk;            unm[k] = um; mmax = fmaxf(mmax, um);
            float ut = ((k == hot) ? H1 : O1) + pk; unt[k] = ut; tmax = fmaxf(tmax, ut);
        }
        float ms = 0.f, ts = 0.f;
        #pragma unroll
        for (int k = 0; k < KCLS; k++) { ms += expf(unm[k] - mmax); ts += expf(unt[k] - tmax); }
        float mlse = mmax + logf(ms), tlse = tmax + logf(ts);
        float EXPL = expf(CL_F);
        #pragma unroll
        for (int k = 0; k < KCLS; k++) {
            float lt = unt[k] - tlse, lm = unm[k] - mlse;
            kl  += expf(lt) * (lt - lm);
            dec -= ((k == hot) ? 1.0f : EXPL) * lm;
        }
    }

    #pragma unroll
    for (int o = 16; o; o >>= 1) {
        g   += __shfl_xor_sync(0xffffffffu, g, o);
        kl  += __shfl_xor_sync(0xffffffffu, kl, o);
        dec += __shfl_xor_sync(0xffffffffu, dec, o);
    }
    if (lane == 0) {
        float Lt = (t == 0) ? dec : kl;
        s_row[warp] = (Lt + d_KLP) * (1.0f / ((float)NCAT * (float)BATCH))
                    + g * (1.0f / ((float)NNUM * (float)BATCH));
    }
    __syncthreads();
    if (threadIdx.x == 0) {
        float s = 0.f;
        #pragma unroll
        for (int i = 0; i < 8; i++) s += s_row[i];
        d_PART[blockIdx.x] = s;
    }
}

__global__ void final_kernel(float* __restrict__ out) {
    __shared__ float s[256];
    float a = 0.f;
    for (int i = threadIdx.x; i < BATCH / 8; i += 256) a += d_PART[i];
    s[threadIdx.x] = a;
    __syncthreads();
    for (int st = 128; st; st >>= 1) {
        if (threadIdx.x < st) s[threadIdx.x] += s[threadIdx.x + st];
        __syncthreads();
    }
    if (threadIdx.x == 0) out[0] = s[0];
}

// ---------------- launch ----------------
extern "C" void kernel_launch(void* const* d_in, const int* in_sizes, int n_in,
                              void* d_out, int out_size) {
    const float* x_num   = (const float*)d_in[0];
    const int*   x_cat_r = (const int*)  d_in[1];
    const int*   t_r     = (const int*)  d_in[2];
    const float* noise   = (const float*)d_in[3];
    const float* gumbel  = (const float*)d_in[4];
    const float* te_w1   = (const float*)d_in[5];
    const float* te_b1   = (const float*)d_in[6];
    const float* te_w2   = (const float*)d_in[7];
    const float* te_b2   = (const float*)d_in[8];
    const float* proj_w  = (const float*)d_in[9];
    const float* proj_b  = (const float*)d_in[10];
    const float* mlp_w1  = (const float*)d_in[11];
    const float* mlp_b1  = (const float*)d_in[12];
    const float* mlp_w2  = (const float*)d_in[13];
    const float* mlp_b2  = (const float*)d_in[14];
    float* out = (float*)d_out;

    float *pE0, *pE1, *pEMB, *pH, *pU, *pOUT;
    cudaGetSymbolAddress((void**)&pE0,  d_E0);
    cudaGetSymbolAddress((void**)&pE1,  d_E1);
    cudaGetSymbolAddress((void**)&pEMB, d_EMB);
    cudaGetSymbolAddress((void**)&pH,   d_H);
    cudaGetSymbolAddress((void**)&pU,   d_U);
    cudaGetSymbolAddress((void**)&pOUT, d_OUT);

    sched_kernel<<<1, 32>>>();
    detect_kernel<<<1, 32>>>(t_r, x_cat_r);
    convert_t_kernel<<<BATCH / 256, 256>>>(t_r);
    convert_cat_kernel<<<(BATCH * NCAT + 255) / 256, 256>>>(x_cat_r);
    temb_kernel<<<dim3(TSTEPS, DIMT / 256), 256>>>();

    // timestep-embedding MLP over 1000 unique t (16x less work than per-row)
    sgemm_kernel<<<dim3(DIMT / BN, (TSTEPS + BM - 1) / BM), 256>>>(
        pE0, te_w1, te_b1, pE1, TSTEPS, DIMT, DIMT, /*silu*/2);
    sgemm_kernel<<<dim3(DIMT / BN, (TSTEPS + BM - 1) / BM), 256>>>(
        pE1, te_w2, te_b2, pEMB, TSTEPS, DIMT, DIMT, /*none*/0);

    sumall_kernel<<<DIMT / 256, 256>>>(proj_w);
    build_h_kernel<<<BATCH, 256>>>(x_num, noise, gumbel, proj_w, proj_b);

    sgemm_kernel<<<dim3(HIDN / BN, BATCH / BM), 256>>>(
        pH, mlp_w1, mlp_b1, pU, BATCH, HIDN, DIMT, /*relu*/1);
    sgemm_kernel<<<dim3((DIN + BN - 1) / BN, BATCH / BM), 256>>>(
        pU, mlp_w2, mlp_b2, pOUT, BATCH, DIN, HIDN, /*none*/0);

    loss_kernel<<<BATCH / 8, 256>>>(noise);
    final_kernel<<<1, 256>>>(out);
}

// round 4
// speedup vs baseline: 5.7644x; 5.7644x over previous
#include <cuda_runtime.h>
#include <math.h>
#include <stdint.h>

// ---------------- problem constants ----------------
#define BATCH  16384
#define NNUM   16
#define NCAT   24
#define KCLS   16
#define CATDIM 384          // NCAT*KCLS
#define DIN    400          // NNUM + CATDIM
#define DIMT   1024
#define HIDN   1024
#define TSTEPS 1000

#define LOGK_F 2.772588722239781f      // log(16) rounded to fp32
#define CL_F   (-69.07755278982137f)   // log(1e-30) in fp32

// ---------------- device scratch (static: no allocs allowed) ----------------
__device__ float d_LOG_A[TSTEPS], d_LOG_1M_A[TSTEPS];
__device__ float d_LOG_CA[TSTEPS], d_LOG_1M_CA[TSTEPS];
__device__ float d_SQAC[TSTEPS], d_SQ1MAC[TSTEPS];
__device__ float d_KLP;                 // kl_prior per row (constant)
__device__ int   d_t64, d_c64;          // dtype sniff flags
__device__ int   d_TT[BATCH];
__device__ int   d_CAT[BATCH * NCAT];
__device__ int   d_SAMP[BATCH * NCAT];
__device__ float d_E0[TSTEPS * DIMT];
__device__ float d_E1[TSTEPS * DIMT];
__device__ float d_EMB[TSTEPS * DIMT];
__device__ float d_SUMALL[DIMT];        // sum of the 384 categorical proj_w rows
__device__ float d_H[(size_t)BATCH * DIMT];
__device__ float d_U[(size_t)BATCH * HIDN];
__device__ float d_OUT[(size_t)BATCH * DIN];
__device__ float d_PART[BATCH / 8];

// ---------------- helpers ----------------
__device__ __forceinline__ float laddexp(float a, float b) {
    float m = fmaxf(a, b);
    return m + logf(expf(a - m) + expf(b - m));
}

__device__ __forceinline__ uint32_t smem_u32(const void* p) {
    return (uint32_t)__cvta_generic_to_shared(p);
}
__device__ __forceinline__ void cpa16(uint32_t dst, const void* src, bool p) {
    int sz = p ? 16 : 0;
    asm volatile("cp.async.cg.shared.global [%0], [%1], 16, %2;\n"
                 :: "r"(dst), "l"(src), "r"(sz));
}

// ---------------- schedules: parallel fp64 + block prefix scan ----------------
__global__ void sched_kernel() {
    __shared__ double s[1024];
    int i = threadIdx.x;
    const double PI = 3.14159265358979323846;
    double la = 0.0;
    if (i < TSTEPS) {
        double u0 = (double)i / (double)TSTEPS;
        double u1 = (double)(i + 1) / (double)TSTEPS;
        double c0 = cos((u0 + 0.008) / 1.008 * PI / 2.0); double ab0 = c0 * c0;
        double c1 = cos((u1 + 0.008) / 1.008 * PI / 2.0); double ab1 = c1 * c1;
        double beta = 1.0 - ab1 / ab0;
        if (beta > 0.999) beta = 0.999;
        la = log(1.0 - beta);
    }
    s[i] = la;
    __syncthreads();
    // Hillis-Steele inclusive scan over 1024 doubles
    #pragma unroll
    for (int off = 1; off < 1024; off <<= 1) {
        double v = (i >= off) ? s[i - off] : 0.0;
        __syncthreads();
        s[i] += v;
        __syncthreads();
    }
    if (i < TSTEPS) {
        double lca = s[i];
        d_LOG_A[i]     = (float)la;
        d_LOG_1M_A[i]  = (float)log(1.0 - exp(la) + 1e-40);
        d_LOG_CA[i]    = (float)lca;
        d_LOG_1M_CA[i] = (float)log(1.0 - exp(lca) + 1e-40);
        double ac = exp(lca);
        d_SQAC[i]   = (float)sqrt(ac);
        d_SQ1MAC[i] = (float)sqrt(1.0 - ac);
    }
    __syncthreads();
    if (i == 0) {
        float lcaT = d_LOG_CA[TSTEPS - 1], l1mT = d_LOG_1M_CA[TSTEPS - 1];
        float hT = laddexp(lcaT, l1mT - LOGK_F);
        float oT = laddexp(CL_F + lcaT, l1mT - LOGK_F);
        d_KLP = (float)NCAT * (expf(hT) * (hT + LOGK_F) + 15.0f * expf(oT) * (oT + LOGK_F));
    }
}

// ---------------- int64 vs int32 sniff + conversion ----------------
__global__ void detect_kernel(const int* __restrict__ traw, const int* __restrict__ craw) {
    if (threadIdx.x != 0) return;
    int z = 1;
    for (int i = 0; i < 64; i++) if (traw[2 * i + 1] != 0) { z = 0; break; }
    d_t64 = z;
    z = 1;
    for (int i = 0; i < 64; i++) if (craw[2 * i + 1] != 0) { z = 0; break; }
    d_c64 = z;
}
__global__ void convert_t_kernel(const int* __restrict__ raw) {
    int i = blockIdx.x * blockDim.x + threadIdx.x;
    if (i < BATCH) d_TT[i] = d_t64 ? raw[2 * i] : raw[i];
}
__global__ void convert_cat_kernel(const int* __restrict__ raw) {
    int i = blockIdx.x * blockDim.x + threadIdx.x;
    if (i < BATCH * NCAT) d_CAT[i] = d_c64 ? raw[2 * i] : raw[i];
}

// ---------------- timestep embedding for all 1000 unique t ----------------
__global__ void temb_kernel() {
    int t = blockIdx.x;
    int j = blockIdx.y * blockDim.x + threadIdx.x;   // 0..1023
    int h = j & 511;
    float freq = expf(-9.210340371976184f * (float)h / 512.0f);
    float arg = (float)t * freq;
    d_E0[t * DIMT + j] = (j < 512) ? cosf(arg) : sinf(arg);
}

// ---------------- SGEMM: C = epi(A@B + bias), row-major, cp.async pipelined ----
#define BM 128
#define BN 128
#define BK 16

__global__ __launch_bounds__(256, 2) void sgemm_kernel(
    const float* __restrict__ A, const float* __restrict__ B,
    const float* __restrict__ bias, float* __restrict__ C,
    int M, int N, int K, int epi)
{
    __shared__ float As[2][BM][BK];
    __shared__ float Bs[2][BK][BN];
    int tid = threadIdx.x;
    int rowBase = blockIdx.y * BM;
    int colBase = blockIdx.x * BN;

    int aRow = tid >> 2;            // 0..63 (two passes: +0, +64)
    int aCol = (tid & 3) * 4;       // 0,4,8,12
    int bRow = tid >> 5;            // 0..7  (two passes: +0, +8)
    int bCol = (tid & 31) * 4;      // 0..124

    int tRow = (tid >> 4) * 8;
    int tCol = (tid & 15) * 8;

    // precomputed smem destinations
    uint32_t sA0[2], sA1[2], sB0[2], sB1[2];
    #pragma unroll
    for (int b = 0; b < 2; b++) {
        sA0[b] = smem_u32(&As[b][aRow][aCol]);
        sA1[b] = smem_u32(&As[b][aRow + 64][aCol]);
        sB0[b] = smem_u32(&Bs[b][bRow][bCol]);
        sB1[b] = smem_u32(&Bs[b][bRow + 8][bCol]);
    }

    // global source predicates / clamped addresses
    bool pa0 = (rowBase + aRow) < M;
    bool pa1 = (rowBase + aRow + 64) < M;
    bool pb  = (colBase + bCol) < N;
    size_t arow0 = (size_t)(pa0 ? rowBase + aRow      : 0) * K + aCol;
    size_t arow1 = (size_t)(pa1 ? rowBase + aRow + 64 : 0) * K + aCol;
    int    bcolc = pb ? colBase + bCol : 0;

    float acc[8][8] = {};
    int S = K / BK;

    // prologue: slab 0 into buffer 0
    {
        cpa16(sA0[0], &A[arow0], pa0);
        cpa16(sA1[0], &A[arow1], pa1);
        cpa16(sB0[0], &B[(size_t)bRow * N + bcolc], pb);
        cpa16(sB1[0], &B[(size_t)(bRow + 8) * N + bcolc], pb);
        asm volatile("cp.async.commit_group;\n" ::: "memory");
    }

    for (int s = 0; s < S; s++) {
        if (s + 1 < S) {
            int nb = (s + 1) & 1;
            int k0 = (s + 1) * BK;
            cpa16(sA0[nb], &A[arow0 + k0], pa0);
            cpa16(sA1[nb], &A[arow1 + k0], pa1);
            cpa16(sB0[nb], &B[(size_t)(k0 + bRow) * N + bcolc], pb);
            cpa16(sB1[nb], &B[(size_t)(k0 + bRow + 8) * N + bcolc], pb);
        }
        asm volatile("cp.async.commit_group;\n" ::: "memory");
        asm volatile("cp.async.wait_group 1;\n" ::: "memory");
        __syncthreads();

        int b = s & 1;
        #pragma unroll
        for (int kk = 0; kk < BK; kk++) {
            float ar[8], br[8];
            #pragma unroll
            for (int i = 0; i < 8; i++) ar[i] = As[b][tRow + i][kk];
            *reinterpret_cast<float4*>(&br[0]) = *reinterpret_cast<const float4*>(&Bs[b][kk][tCol]);
            *reinterpret_cast<float4*>(&br[4]) = *reinterpret_cast<const float4*>(&Bs[b][kk][tCol + 4]);
            #pragma unroll
            for (int i = 0; i < 8; i++)
                #pragma unroll
                for (int j = 0; j < 8; j++)
                    acc[i][j] = fmaf(ar[i], br[j], acc[i][j]);
        }
        __syncthreads();
    }

    // epilogue (N is always a multiple of 4; gc aligned to 4)
    #pragma unroll
    for (int i = 0; i < 8; i++) {
        int gr = rowBase + tRow + i;
        if (gr >= M) continue;
        #pragma unroll
        for (int j0 = 0; j0 < 8; j0 += 4) {
            int gc = colBase + tCol + j0;
            if (gc >= N) continue;
            float4 v;
            float t0 = acc[i][j0 + 0] + bias[gc + 0];
            float t1 = acc[i][j0 + 1] + bias[gc + 1];
            float t2 = acc[i][j0 + 2] + bias[gc + 2];
            float t3 = acc[i][j0 + 3] + bias[gc + 3];
            if (epi == 1) {
                t0 = fmaxf(t0, 0.f); t1 = fmaxf(t1, 0.f);
                t2 = fmaxf(t2, 0.f); t3 = fmaxf(t3, 0.f);
            } else if (epi == 2) {
                t0 = t0 / (1.f + expf(-t0)); t1 = t1 / (1.f + expf(-t1));
                t2 = t2 / (1.f + expf(-t2)); t3 = t3 / (1.f + expf(-t3));
            }
            v.x = t0; v.y = t1; v.z = t2; v.w = t3;
            *reinterpret_cast<float4*>(&C[(size_t)gr * N + gc]) = v;
        }
    }
}

// ---------------- sum of categorical proj_w rows ----------------
__global__ void sumall_kernel(const float* __restrict__ proj_w) {
    int j = blockIdx.x * blockDim.x + threadIdx.x;
    if (j >= DIMT) return;
    float s = 0.f;
    for (int r = NNUM; r < DIN; r++) s += proj_w[(size_t)r * DIMT + j];
    d_SUMALL[j] = s;
}

// ---------------- build h = x_in@proj_w + proj_b + emb (one block per row) ----
__global__ __launch_bounds__(256) void build_h_kernel(
    const float* __restrict__ x_num, const float* __restrict__ noise,
    const float* __restrict__ gumbel, const float* __restrict__ proj_w,
    const float* __restrict__ proj_b)
{
    int b = blockIdx.x;
    int tid = threadIdx.x;
    __shared__ float s_xnt[NNUM];
    __shared__ int   s_samp[NCAT];
    int t = d_TT[b];

    if (tid < NNUM)
        s_xnt[tid] = d_SQAC[t] * x_num[b * NNUM + tid] + d_SQ1MAC[t] * noise[b * NNUM + tid];

    if (tid < NCAT) {
        int hot = d_CAT[b * NCAT + tid];
        float hv = laddexp(d_LOG_CA[t], d_LOG_1M_CA[t] - LOGK_F);
        float ov = laddexp(CL_F + d_LOG_CA[t], d_LOG_1M_CA[t] - LOGK_F);
        const float* gp = gumbel + (size_t)b * CATDIM + tid * KCLS;
        float best = -1e30f; int bi = 0;
        #pragma unroll
        for (int k = 0; k < KCLS; k++) {
            float g = -logf(-logf(gp[k] + 1e-30f) + 1e-30f);
            float v = g + ((k == hot) ? hv : ov);
            if (v > best) { best = v; bi = k; }
        }
        s_samp[tid] = bi;
        d_SAMP[b * NCAT + tid] = bi;
    }
    __syncthreads();

    #pragma unroll
    for (int r = 0; r < DIMT / 256; r++) {
        int j = tid + 256 * r;
        float acc = d_EMB[t * DIMT + j] + proj_b[j] + CL_F * d_SUMALL[j];
        #pragma unroll
        for (int i = 0; i < NNUM; i++) acc += s_xnt[i] * proj_w[i * DIMT + j];
        #pragma unroll
        for (int c = 0; c < NCAT; c++)
            acc -= CL_F * proj_w[(size_t)(NNUM + c * KCLS + s_samp[c]) * DIMT + j];
        d_H[(size_t)b * DIMT + j] = acc;
    }
}

// ---------------- per-row loss (1 warp per row, 8 rows per block) ----------
__global__ __launch_bounds__(256) void loss_kernel(const float* __restrict__ noise) {
    int warp = threadIdx.x >> 5, lane = threadIdx.x & 31;
    int b = blockIdx.x * 8 + warp;
    __shared__ float s_row[8];
    int t = d_TT[b];
    int tm1 = (t > 0) ? t - 1 : 0;
    const float* outp = d_OUT + (size_t)b * DIN;

    float g = 0.f;
    if (lane < NNUM) { float d = noise[b * NNUM + lane] - outp[lane]; g = d * d; }

    float kl = 0.f, dec = 0.f;
    if (lane < NCAT) {
        int hot = d_CAT[b * NCAT + lane];
        int sm  = d_SAMP[b * NCAT + lane];
        const float* oc = outp + NNUM + lane * KCLS;
        float v[KCLS];
        float mx = -1e30f;
        #pragma unroll
        for (int k = 0; k < KCLS; k++) { v[k] = oc[k]; mx = fmaxf(mx, v[k]); }
        float se = 0.f;
        #pragma unroll
        for (int k = 0; k < KCLS; k++) se += expf(v[k] - mx);
        float lse = mx + logf(se);

        float PH = laddexp(d_LOG_A[t], d_LOG_1M_A[t] - LOGK_F);
        float PO = laddexp(CL_F + d_LOG_A[t], d_LOG_1M_A[t] - LOGK_F);
        float H1, O1;
        if (t == 0) { H1 = 0.f; O1 = CL_F; }
        else {
            H1 = laddexp(d_LOG_CA[tm1], d_LOG_1M_CA[tm1] - LOGK_F);
            O1 = laddexp(CL_F + d_LOG_CA[tm1], d_LOG_1M_CA[tm1] - LOGK_F);
        }

        float unm[KCLS], unt[KCLS];
        float mmax = -1e30f, tmax = -1e30f;
        #pragma unroll
        for (int k = 0; k < KCLS; k++) {
            float lx0 = v[k] - lse;
            float ev  = (t == 0) ? lx0
                                 : laddexp(lx0 + d_LOG_CA[tm1], d_LOG_1M_CA[tm1] - LOGK_F);
            float pk  = (k == sm) ? PH : PO;
            float um = ev + pk;            unm[k] = um; mmax = fmaxf(mmax, um);
            float ut = ((k == hot) ? H1 : O1) + pk; unt[k] = ut; tmax = fmaxf(tmax, ut);
        }
        float ms = 0.f, ts = 0.f;
        #pragma unroll
        for (int k = 0; k < KCLS; k++) { ms += expf(unm[k] - mmax); ts += expf(unt[k] - tmax); }
        float mlse = mmax + logf(ms), tlse = tmax + logf(ts);
        float EXPL = expf(CL_F);
        #pragma unroll
        for (int k = 0; k < KCLS; k++) {
            float lt = unt[k] - tlse, lm = unm[k] - mlse;
            kl  += expf(lt) * (lt - lm);
            dec -= ((k == hot) ? 1.0f : EXPL) * lm;
        }
    }

    #pragma unroll
    for (int o = 16; o; o >>= 1) {
        g   += __shfl_xor_sync(0xffffffffu, g, o);
        kl  += __shfl_xor_sync(0xffffffffu, kl, o);
        dec += __shfl_xor_sync(0xffffffffu, dec, o);
    }
    if (lane == 0) {
        float Lt = (t == 0) ? dec : kl;
        s_row[warp] = (Lt + d_KLP) * (1.0f / ((float)NCAT * (float)BATCH))
                    + g * (1.0f / ((float)NNUM * (float)BATCH));
    }
    __syncthreads();
    if (threadIdx.x == 0) {
        float s = 0.f;
        #pragma unroll
        for (int i = 0; i < 8; i++) s += s_row[i];
        d_PART[blockIdx.x] = s;
    }
}

__global__ void final_kernel(float* __restrict__ out) {
    __shared__ float s[256];
    float a = 0.f;
    for (int i = threadIdx.x; i < BATCH / 8; i += 256) a += d_PART[i];
    s[threadIdx.x] = a;
    __syncthreads();
    for (int st = 128; st; st >>= 1) {
        if (threadIdx.x < st) s[threadIdx.x] += s[threadIdx.x + st];
        __syncthreads();
    }
    if (threadIdx.x == 0) out[0] = s[0];
}

// ---------------- launch ----------------
extern "C" void kernel_launch(void* const* d_in, const int* in_sizes, int n_in,
                              void* d_out, int out_size) {
    const float* x_num   = (const float*)d_in[0];
    const int*   x_cat_r = (const int*)  d_in[1];
    const int*   t_r     = (const int*)  d_in[2];
    const float* noise   = (const float*)d_in[3];
    const float* gumbel  = (const float*)d_in[4];
    const float* te_w1   = (const float*)d_in[5];
    const float* te_b1   = (const float*)d_in[6];
    const float* te_w2   = (const float*)d_in[7];
    const float* te_b2   = (const float*)d_in[8];
    const float* proj_w  = (const float*)d_in[9];
    const float* proj_b  = (const float*)d_in[10];
    const float* mlp_w1  = (const float*)d_in[11];
    const float* mlp_b1  = (const float*)d_in[12];
    const float* mlp_w2  = (const float*)d_in[13];
    const float* mlp_b2  = (const float*)d_in[14];
    float* out = (float*)d_out;

    float *pE0, *pE1, *pEMB, *pH, *pU, *pOUT;
    cudaGetSymbolAddress((void**)&pE0,  d_E0);
    cudaGetSymbolAddress((void**)&pE1,  d_E1);
    cudaGetSymbolAddress((void**)&pEMB, d_EMB);
    cudaGetSymbolAddress((void**)&pH,   d_H);
    cudaGetSymbolAddress((void**)&pU,   d_U);
    cudaGetSymbolAddress((void**)&pOUT, d_OUT);

    sched_kernel<<<1, 1024>>>();
    detect_kernel<<<1, 32>>>(t_r, x_cat_r);
    convert_t_kernel<<<BATCH / 256, 256>>>(t_r);
    convert_cat_kernel<<<(BATCH * NCAT + 255) / 256, 256>>>(x_cat_r);
    temb_kernel<<<dim3(TSTEPS, DIMT / 256), 256>>>();

    // timestep-embedding MLP over 1000 unique t (16x less work than per-row)
    sgemm_kernel<<<dim3(DIMT / BN, (TSTEPS + BM - 1) / BM), 256>>>(
        pE0, te_w1, te_b1, pE1, TSTEPS, DIMT, DIMT, /*silu*/2);
    sgemm_kernel<<<dim3(DIMT / BN, (TSTEPS + BM - 1) / BM), 256>>>(
        pE1, te_w2, te_b2, pEMB, TSTEPS, DIMT, DIMT, /*none*/0);

    sumall_kernel<<<DIMT / 256, 256>>>(proj_w);
    build_h_kernel<<<BATCH, 256>>>(x_num, noise, gumbel, proj_w, proj_b);

    sgemm_kernel<<<dim3(HIDN / BN, BATCH / BM), 256>>>(
        pH, mlp_w1, mlp_b1, pU, BATCH, HIDN, DIMT, /*relu*/1);
    sgemm_kernel<<<dim3((DIN + BN - 1) / BN, BATCH / BM), 256>>>(
        pU, mlp_w2, mlp_b2, pOUT, BATCH, DIN, HIDN, /*none*/0);

    loss_kernel<<<BATCH / 8, 256>>>(noise);
    final_kernel<<<1, 256>>>(out);
}

// round 7
// speedup vs baseline: 9.3851x; 1.6281x over previous
#include <cuda_runtime.h>
#include <cuda_bf16.h>
#include <math.h>
#include <stdint.h>

// ---------------- problem constants ----------------
#define BATCH  16384
#define NNUM   16
#define NCAT   24
#define KCLS   16
#define CATDIM 384
#define DIN    400
#define KPAD   512          // padded DIN for proj GEMM
#define DIMT   1024
#define HIDN   1024
#define NPAD2  512          // padded DIN for mlp2 output
#define TSTEPS 1000
#define TPAD   1024

#define LOGK_F 2.772588722239781f
#define CL_F   (-69.07755278982137f)

// ---------------- device scratch ----------------
__device__ float d_LOG_A[TSTEPS], d_LOG_1M_A[TSTEPS];
__device__ float d_LOG_CA[TSTEPS], d_LOG_1M_CA[TSTEPS];
__device__ float d_SQAC[TSTEPS], d_SQ1MAC[TSTEPS];
__device__ float d_KLP;
__device__ int   d_t64, d_c64;
__device__ int   d_TT[BATCH];
__device__ int   d_CAT[BATCH * NCAT];
__device__ int   d_SAMP[BATCH * NCAT];

__device__ __nv_bfloat16 d_E0H[TPAD * DIMT], d_E0L[TPAD * DIMT];
__device__ __nv_bfloat16 d_E1H[TPAD * DIMT], d_E1L[TPAD * DIMT];
__device__ float         d_EMB[TPAD * DIMT];
__device__ __nv_bfloat16 d_W1TH[DIMT * DIMT], d_W1TL[DIMT * DIMT];   // te_w1^T
__device__ __nv_bfloat16 d_W2TH[DIMT * DIMT], d_W2TL[DIMT * DIMT];   // te_w2^T
__device__ __nv_bfloat16 d_M1TH[HIDN * DIMT], d_M1TL[HIDN * DIMT];   // mlp_w1^T
__device__ __nv_bfloat16 d_M2TH[NPAD2 * HIDN], d_M2TL[NPAD2 * HIDN]; // mlp_w2^T padded
__device__ __nv_bfloat16 d_PJTH[DIMT * KPAD], d_PJTL[DIMT * KPAD];   // proj_w^T padded
__device__ __nv_bfloat16 d_XINH[(size_t)BATCH * KPAD], d_XINL[(size_t)BATCH * KPAD];
__device__ __nv_bfloat16 d_HH[(size_t)BATCH * DIMT], d_HL[(size_t)BATCH * DIMT];
__device__ __nv_bfloat16 d_UH[(size_t)BATCH * DIMT], d_UL[(size_t)BATCH * DIMT];
__device__ float         d_OUT[(size_t)BATCH * NPAD2];
__device__ float         d_B2P[NPAD2];
__device__ float d_PART[BATCH / 8];

// ---------------- helpers ----------------
__device__ __forceinline__ float laddexp(float a, float b) {
    float m = fmaxf(a, b);
    return m + logf(expf(a - m) + expf(b - m));
}
__device__ __forceinline__ uint32_t smem_u32(const void* p) {
    return (uint32_t)__cvta_generic_to_shared(p);
}
#define SWZ128(o) ((o) ^ (((o) >> 3) & 0x70))

// ---------------- schedules ----------------
__global__ void sched_kernel() {
    __shared__ double s[1024];
    int i = threadIdx.x;
    const double PI = 3.14159265358979323846;
    double la = 0.0;
    if (i < TSTEPS) {
        double u0 = (double)i / (double)TSTEPS;
        double u1 = (double)(i + 1) / (double)TSTEPS;
        double c0 = cos((u0 + 0.008) / 1.008 * PI / 2.0); double ab0 = c0 * c0;
        double c1 = cos((u1 + 0.008) / 1.008 * PI / 2.0); double ab1 = c1 * c1;
        double beta = 1.0 - ab1 / ab0;
        if (beta > 0.999) beta = 0.999;
        la = log(1.0 - beta);
    }
    s[i] = la;
    __syncthreads();
    #pragma unroll
    for (int off = 1; off < 1024; off <<= 1) {
        double v = (i >= off) ? s[i - off] : 0.0;
        __syncthreads();
        s[i] += v;
        __syncthreads();
    }
    if (i < TSTEPS) {
        double lca = s[i];
        d_LOG_A[i]     = (float)la;
        d_LOG_1M_A[i]  = (float)log(1.0 - exp(la) + 1e-40);
        d_LOG_CA[i]    = (float)lca;
        d_LOG_1M_CA[i] = (float)log(1.0 - exp(lca) + 1e-40);
        double ac = exp(lca);
        d_SQAC[i]   = (float)sqrt(ac);
        d_SQ1MAC[i] = (float)sqrt(1.0 - ac);
    }
    __syncthreads();
    if (i == 0) {
        float lcaT = d_LOG_CA[TSTEPS - 1], l1mT = d_LOG_1M_CA[TSTEPS - 1];
        float hT = laddexp(lcaT, l1mT - LOGK_F);
        float oT = laddexp(CL_F + lcaT, l1mT - LOGK_F);
        d_KLP = (float)NCAT * (expf(hT) * (hT + LOGK_F) + 15.0f * expf(oT) * (oT + LOGK_F));
    }
}

// ---------------- dtype sniff + conversions ----------------
__global__ void detect_kernel(const int* __restrict__ traw, const int* __restrict__ craw) {
    if (threadIdx.x != 0) return;
    int z = 1;
    for (int i = 0; i < 64; i++) if (traw[2 * i + 1] != 0) { z = 0; break; }
    d_t64 = z;
    z = 1;
    for (int i = 0; i < 64; i++) if (craw[2 * i + 1] != 0) { z = 0; break; }
    d_c64 = z;
}
__global__ void convert_t_kernel(const int* __restrict__ raw) {
    int i = blockIdx.x * blockDim.x + threadIdx.x;
    if (i < BATCH) d_TT[i] = d_t64 ? raw[2 * i] : raw[i];
}
__global__ void convert_cat_kernel(const int* __restrict__ raw) {
    int i = blockIdx.x * blockDim.x + threadIdx.x;
    if (i < BATCH * NCAT) d_CAT[i] = d_c64 ? raw[2 * i] : raw[i];
}
__global__ void pad_bias_kernel(const float* __restrict__ b2) {
    int i = blockIdx.x * blockDim.x + threadIdx.x;
    if (i < NPAD2) d_B2P[i] = (i < DIN) ? b2[i] : 0.f;
}

// ---------------- timestep embedding (hi/lo bf16, padded rows zero) --------
__global__ void temb_kernel() {
    int t = blockIdx.x;
    int j = blockIdx.y * blockDim.x + threadIdx.x;
    float v = 0.f;
    if (t < TSTEPS) {
        int h = j & 511;
        float freq = expf(-9.210340371976184f * (float)h / 512.0f);
        float arg = (float)t * freq;
        v = (j < 512) ? cosf(arg) : sinf(arg);
    }
    __nv_bfloat16 hi = __float2bfloat16(v);
    __nv_bfloat16 lo = __float2bfloat16(v - __bfloat162float(hi));
    d_E0H[t * DIMT + j] = hi;
    d_E0L[t * DIMT + j] = lo;
}

// ---------------- transpose + hi/lo split: out[c, r] = in[r, c] ----------
__global__ void transpose_split(const float* __restrict__ in, int R, int C,
                                int Rpad, __nv_bfloat16* __restrict__ oh,
                                __nv_bfloat16* __restrict__ ol) {
    __shared__ float tl[32][33];
    int c0 = blockIdx.x * 32, r0 = blockIdx.y * 32;
    #pragma unroll
    for (int k = 0; k < 4; k++) {
        int r = r0 + threadIdx.y + k * 8;
        int c = c0 + threadIdx.x;
        float v = (r < R && c < C) ? in[(size_t)r * C + c] : 0.f;
        tl[threadIdx.x][threadIdx.y + k * 8] = v;
    }
    __syncthreads();
    #pragma unroll
    for (int k = 0; k < 4; k++) {
        int c = c0 + threadIdx.y + k * 8;   // out row
        int r = r0 + threadIdx.x;           // out col
        float v = tl[threadIdx.y + k * 8][threadIdx.x];
        __nv_bfloat16 h = __float2bfloat16(v);
        oh[(size_t)c * Rpad + r] = h;
        ol[(size_t)c * Rpad + r] = __float2bfloat16(v - __bfloat162float(h));
    }
}

// ---------------- build x_in (hi/lo bf16, padded to 512) + sampling -------
__global__ __launch_bounds__(128) void build_xin_kernel(
    const float* __restrict__ x_num, const float* __restrict__ noise,
    const float* __restrict__ gumbel) {
    int b = blockIdx.x;
    int tid = threadIdx.x;
    __shared__ float s_x[NNUM];
    __shared__ int   s_s[NCAT];
    int t = d_TT[b];

    if (tid < NNUM)
        s_x[tid] = d_SQAC[t] * x_num[b * NNUM + tid] + d_SQ1MAC[t] * noise[b * NNUM + tid];
    if (tid < NCAT) {
        int hot = d_CAT[b * NCAT + tid];
        float hv = laddexp(d_LOG_CA[t], d_LOG_1M_CA[t] - LOGK_F);
        float ov = laddexp(CL_F + d_LOG_CA[t], d_LOG_1M_CA[t] - LOGK_F);
        const float* gp = gumbel + (size_t)b * CATDIM + tid * KCLS;
        float best = -1e30f; int bi = 0;
        #pragma unroll
        for (int k = 0; k < KCLS; k++) {
            float g = -logf(-logf(gp[k] + 1e-30f) + 1e-30f);
            float v = g + ((k == hot) ? hv : ov);
            if (v > best) { best = v; bi = k; }
        }
        s_s[tid] = bi;
        d_SAMP[b * NCAT + tid] = bi;
    }
    __syncthreads();

    const __nv_bfloat16 clh = __float2bfloat16(CL_F);
    const __nv_bfloat16 cll = __float2bfloat16(CL_F - __bfloat162float(clh));
    #pragma unroll
    for (int rr = 0; rr < KPAD / 128; rr++) {
        int j = tid + rr * 128;
        __nv_bfloat16 h, l;
        if (j < NNUM) {
            float v = s_x[j];
            h = __float2bfloat16(v);
            l = __float2bfloat16(v - __bfloat162float(h));
        } else if (j < DIN) {
            int c = (j - NNUM) >> 4, k = (j - NNUM) & 15;
            if (k == s_s[c]) { h = __float2bfloat16(0.f); l = h; }
            else { h = clh; l = cll; }
        } else {
            h = __float2bfloat16(0.f); l = h;
        }
        d_XINH[(size_t)b * KPAD + j] = h;
        d_XINL[(size_t)b * KPAD + j] = l;
    }
}

// ---------------- bf16 mma.sync GEMM: D = sum3(A@B^T) + bias --------------
// A[M,K] hi/lo (K-major), B[N,K] hi/lo (K-major, weights pre-transposed).
// 3 passes: Ahi*Bhi + Alo*Bhi + Ahi*Blo accumulated in fp32 regs.
// mode 0: fp32 out   1: relu->hi/lo   2: silu->hi/lo   3: +emb[t[row]]->hi/lo
// Block 128x128, 8 warps (4Mx2N), warp 32x64, BK=64 elems, 2-stage cp.async.
#define GSMEM_BYTES 65536
__global__ __launch_bounds__(256, 2) void mma_gemm(
    const __nv_bfloat16* __restrict__ Ahi, const __nv_bfloat16* __restrict__ Alo,
    const __nv_bfloat16* __restrict__ Bhi, const __nv_bfloat16* __restrict__ Blo,
    const float* __restrict__ bias,
    float* __restrict__ outF, __nv_bfloat16* __restrict__ outH, __nv_bfloat16* __restrict__ outL,
    const float* __restrict__ emb,
    int Kelem, int ldOut, int mode)
{
    extern __shared__ char smem[];
    const uint32_t sbA = smem_u32(smem);            // 2 stages x 16KB
    const uint32_t sbB = sbA + 32768;               // 2 stages x 16KB
    int tid = threadIdx.x, wid = tid >> 5, lane = tid & 31;
    int wm = (wid & 3) * 32, wn = (wid >> 2) * 64;
    int rowBase = blockIdx.y * 128, colBase = blockIdx.x * 128;

    int KS = Kelem >> 6;
    int NSLAB = 3 * KS;

    // cp.async mapping: 1024 16B-chunks per tile, 4 per thread (same row)
    int c0i = tid * 4;
    int ldRow = c0i >> 3;
    int ldUn  = c0i & 7;           // 0 or 4

    float acc[2][8][4];
    #pragma unroll
    for (int a = 0; a < 2; a++)
        #pragma unroll
        for (int b = 0; b < 8; b++)
            #pragma unroll
            for (int c = 0; c < 4; c++) acc[a][b][c] = 0.f;

    auto issue = [&](int s, int st) {
        int p = s / KS;
        int kb = (s - p * KS) << 6;
        const __nv_bfloat16* As = (p == 1) ? Alo : Ahi;
        const __nv_bfloat16* Bs = (p == 2) ? Blo : Bhi;
        const __nv_bfloat16* ga = As + (size_t)(rowBase + ldRow) * Kelem + kb + ldUn * 8;
        const __nv_bfloat16* gb = Bs + (size_t)(colBase + ldRow) * Kelem + kb + ldUn * 8;
        uint32_t da = sbA + st * 16384;
        uint32_t db = sbB + st * 16384;
        #pragma unroll
        for (int q = 0; q < 4; q++) {
            uint32_t off = SWZ128(ldRow * 128 + (ldUn + q) * 16);
            asm volatile("cp.async.cg.shared.global [%0], [%1], 16;"
                         :: "r"(da + off), "l"(ga + q * 8));
            asm volatile("cp.async.cg.shared.global [%0], [%1], 16;"
                         :: "r"(db + off), "l"(gb + q * 8));
        }
    };

    issue(0, 0);
    asm volatile("cp.async.commit_group;\n" ::: "memory");

    // ldmatrix per-lane address components
    int aRowC = wm + (lane & 15);
    int aKC   = (lane & 16);            // byte offset (16B = 8 elems)
    int bRowC = wn + (lane & 7) + ((lane & 16) >> 1);
    int bKC   = (lane & 8) * 2;         // byte offset

    for (int s = 0; s < NSLAB; s++) {
        if (s + 1 < NSLAB) issue(s + 1, (s + 1) & 1);
        asm volatile("cp.async.commit_group;\n" ::: "memory");
        asm volatile("cp.async.wait_group 1;\n" ::: "memory");
        __syncthreads();

        uint32_t baA = sbA + (s & 1) * 16384;
        uint32_t baB = sbB + (s & 1) * 16384;
        #pragma unroll
        for (int kk = 0; kk < 4; kk++) {
            uint32_t aF[2][4], bF[4][4];
            #pragma unroll
            for (int mi = 0; mi < 2; mi++) {
                int off = (aRowC + mi * 16) * 128 + kk * 32 + aKC;
                uint32_t ad = baA + SWZ128(off);
                asm volatile("ldmatrix.sync.aligned.m8n8.x4.shared.b16 {%0,%1,%2,%3}, [%4];"
                    : "=r"(aF[mi][0]), "=r"(aF[mi][1]), "=r"(aF[mi][2]), "=r"(aF[mi][3])
                    : "r"(ad));
            }
            #pragma unroll
            for (int nt = 0; nt < 4; nt++) {
                int off = (bRowC + nt * 16) * 128 + kk * 32 + bKC;
                uint32_t bd = baB + SWZ128(off);
                asm volatile("ldmatrix.sync.aligned.m8n8.x4.shared.b16 {%0,%1,%2,%3}, [%4];"
                    : "=r"(bF[nt][0]), "=r"(bF[nt][1]), "=r"(bF[nt][2]), "=r"(bF[nt][3])
                    : "r"(bd));
            }
            #pragma unroll
            for (int mi = 0; mi < 2; mi++) {
                #pragma unroll
                for (int nt = 0; nt < 4; nt++) {
                    asm volatile(
                        "mma.sync.aligned.m16n8k16.row.col.f32.bf16.bf16.f32 "
                        "{%0,%1,%2,%3}, {%4,%5,%6,%7}, {%8,%9}, {%0,%1,%2,%3};"
                        : "+f"(acc[mi][nt * 2][0]), "+f"(acc[mi][nt * 2][1]),
                          "+f"(acc[mi][nt * 2][2]), "+f"(acc[mi][nt * 2][3])
                        : "r"(aF[mi][0]), "r"(aF[mi][1]), "r"(aF[mi][2]), "r"(aF[mi][3]),
                          "r"(bF[nt][0]), "r"(bF[nt][1]));
                    asm volatile(
                        "mma.sync.aligned.m16n8k16.row.col.f32.bf16.bf16.f32 "
                        "{%0,%1,%2,%3}, {%4,%5,%6,%7}, {%8,%9}, {%0,%1,%2,%3};"
                        : "+f"(acc[mi][nt * 2 + 1][0]), "+f"(acc[mi][nt * 2 + 1][1]),
                          "+f"(acc[mi][nt * 2 + 1][2]), "+f"(acc[mi][nt * 2 + 1][3])
                        : "r"(aF[mi][0]), "r"(aF[mi][1]), "r"(aF[mi][2]), "r"(aF[mi][3]),
                          "r"(bF[nt][2]), "r"(bF[nt][3]));
                }
            }
        }
        __syncthreads();
    }

    // ---------------- epilogue ----------------
    #pragma unroll
    for (int mi = 0; mi < 2; mi++) {
        #pragma unroll
        for (int half = 0; half < 2; half++) {
            int r = rowBase + wm + mi * 16 + (lane >> 2) + half * 8;
            int tE = (mode == 3) ? d_TT[r] : 0;
            #pragma unroll
            for (int ni = 0; ni < 8; ni++) {
                int c = colBase + wn + ni * 8 + (lane & 3) * 2;
                float v0 = acc[mi][ni][half * 2 + 0] + bias[c];
                float v1 = acc[mi][ni][half * 2 + 1] + bias[c + 1];
                if (mode == 0) {
                    float2 v; v.x = v0; v.y = v1;
                    *reinterpret_cast<float2*>(&outF[(size_t)r * ldOut + c]) = v;
                } else {
                    if (mode == 1) {
                        v0 = fmaxf(v0, 0.f); v1 = fmaxf(v1, 0.f);
                    } else if (mode == 2) {
                        v0 = v0 / (1.f + expf(-v0)); v1 = v1 / (1.f + expf(-v1));
                    } else {
                        v0 += emb[(size_t)tE * DIMT + c];
                        v1 += emb[(size_t)tE * DIMT + c + 1];
                    }
                    __nv_bfloat16 h0 = __float2bfloat16(v0), h1 = __float2bfloat16(v1);
                    __nv_bfloat162 hh, ll;
                    hh.x = h0; hh.y = h1;
                    ll.x = __float2bfloat16(v0 - __bfloat162float(h0));
                    ll.y = __float2bfloat16(v1 - __bfloat162float(h1));
                    *reinterpret_cast<__nv_bfloat162*>(&outH[(size_t)r * ldOut + c]) = hh;
                    *reinterpret_cast<__nv_bfloat162*>(&outL[(size_t)r * ldOut + c]) = ll;
                }
            }
        }
    }
}

// ---------------- per-row loss (OUT stride = NPAD2) -----------------------
__global__ __launch_bounds__(256) void loss_kernel(const float* __restrict__ noise) {
    int warp = threadIdx.x >> 5, lane = threadIdx.x & 31;
    int b = blockIdx.x * 8 + warp;
    __shared__ float s_row[8];
    int t = d_TT[b];
    int tm1 = (t > 0) ? t - 1 : 0;
    const float* outp = d_OUT + (size_t)b * NPAD2;

    float g = 0.f;
    if (lane < NNUM) { float d = noise[b * NNUM + lane] - outp[lane]; g = d * d; }

    float kl = 0.f, dec = 0.f;
    if (lane < NCAT) {
        int hot = d_CAT[b * NCAT + lane];
        int sm  = d_SAMP[b * NCAT + lane];
        const float* oc = outp + NNUM + lane * KCLS;
        float v[KCLS];
        float mx = -1e30f;
        #pragma unroll
        for (int k = 0; k < KCLS; k++) { v[k] = oc[k]; mx = fmaxf(mx, v[k]); }
        float se = 0.f;
        #pragma unroll
        for (int k = 0; k < KCLS; k++) se += expf(v[k] - mx);
        float lse = mx + logf(se);

        float PH = laddexp(d_LOG_A[t], d_LOG_1M_A[t] - LOGK_F);
        float PO = laddexp(CL_F + d_LOG_A[t], d_LOG_1M_A[t] - LOGK_F);
        float H1, O1;
        if (t == 0) { H1 = 0.f; O1 = CL_F; }
        else {
            H1 = laddexp(d_LOG_CA[tm1], d_LOG_1M_CA[tm1] - LOGK_F);
            O1 = laddexp(CL_F + d_LOG_CA[tm1], d_LOG_1M_CA[tm1] - LOGK_F);
        }

        float unm[KCLS], unt[KCLS];
        float mmax = -1e30f, tmax = -1e30f;
        #pragma unroll
        for (int k = 0; k < KCLS; k++) {
            float lx0 = v[k] - lse;
            float ev  = (t == 0) ? lx0
                                 : laddexp(lx0 + d_LOG_CA[tm1], d_LOG_1M_CA[tm1] - LOGK_F);
            float pk  = (k == sm) ? PH : PO;
            float um = ev + pk;            unm[k] = um; mmax = fmaxf(mmax, um);
            float ut = ((k == hot) ? H1 : O1) + pk; unt[k] = ut; tmax = fmaxf(tmax, ut);
        }
        float ms = 0.f, ts = 0.f;
        #pragma unroll
        for (int k = 0; k < KCLS; k++) { ms += expf(unm[k] - mmax); ts += expf(unt[k] - tmax); }
        float mlse = mmax + logf(ms), tlse = tmax + logf(ts);
        float EXPL = expf(CL_F);
        #pragma unroll
        for (int k = 0; k < KCLS; k++) {
            float lt = unt[k] - tlse, lm = unm[k] - mlse;
            kl  += expf(lt) * (lt - lm);
            dec -= ((k == hot) ? 1.0f : EXPL) * lm;
        }
    }

    #pragma unroll
    for (int o = 16; o; o >>= 1) {
        g   += __shfl_xor_sync(0xffffffffu, g, o);
        kl  += __shfl_xor_sync(0xffffffffu, kl, o);
        dec += __shfl_xor_sync(0xffffffffu, dec, o);
    }
    if (lane == 0) {
        float Lt = (t == 0) ? dec : kl;
        s_row[warp] = (Lt + d_KLP) * (1.0f / ((float)NCAT * (float)BATCH))
                    + g * (1.0f / ((float)NNUM * (float)BATCH));
    }
    __syncthreads();
    if (threadIdx.x == 0) {
        float s = 0.f;
        #pragma unroll
        for (int i = 0; i < 8; i++) s += s_row[i];
        d_PART[blockIdx.x] = s;
    }
}

__global__ void final_kernel(float* __restrict__ out) {
    __shared__ float s[256];
    float a = 0.f;
    for (int i = threadIdx.x; i < BATCH / 8; i += 256) a += d_PART[i];
    s[threadIdx.x] = a;
    __syncthreads();
    for (int st = 128; st; st >>= 1) {
        if (threadIdx.x < st) s[threadIdx.x] += s[threadIdx.x + st];
        __syncthreads();
    }
    if (threadIdx.x == 0) out[0] = s[0];
}

// ---------------- launch ----------------
extern "C" void kernel_launch(void* const* d_in, const int* in_sizes, int n_in,
                              void* d_out, int out_size) {
    const float* x_num   = (const float*)d_in[0];
    const int*   x_cat_r = (const int*)  d_in[1];
    const int*   t_r     = (const int*)  d_in[2];
    const float* noise   = (const float*)d_in[3];
    const float* gumbel  = (const float*)d_in[4];
    const float* te_w1   = (const float*)d_in[5];
    const float* te_b1   = (const float*)d_in[6];
    const float* te_w2   = (const float*)d_in[7];
    const float* te_b2   = (const float*)d_in[8];
    const float* proj_w  = (const float*)d_in[9];
    const float* proj_b  = (const float*)d_in[10];
    const float* mlp_w1  = (const float*)d_in[11];
    const float* mlp_b1  = (const float*)d_in[12];
    const float* mlp_w2  = (const float*)d_in[13];
    const float* mlp_b2  = (const float*)d_in[14];
    float* out = (float*)d_out;

    cudaFuncSetAttribute(mma_gemm, cudaFuncAttributeMaxDynamicSharedMemorySize, GSMEM_BYTES);

    __nv_bfloat16 *pE0H, *pE0L, *pE1H, *pE1L;
    __nv_bfloat16 *pW1H, *pW1L, *pW2H, *pW2L, *pM1H, *pM1L, *pM2H, *pM2L, *pPJH, *pPJL;
    __nv_bfloat16 *pXIH, *pXIL, *pHH, *pHL, *pUH, *pUL;
    float *pEMB, *pOUT, *pB2;
    cudaGetSymbolAddress((void**)&pE0H, d_E0H); cudaGetSymbolAddress((void**)&pE0L, d_E0L);
    cudaGetSymbolAddress((void**)&pE1H, d_E1H); cudaGetSymbolAddress((void**)&pE1L, d_E1L);
    cudaGetSymbolAddress((void**)&pW1H, d_W1TH); cudaGetSymbolAddress((void**)&pW1L, d_W1TL);
    cudaGetSymbolAddress((void**)&pW2H, d_W2TH); cudaGetSymbolAddress((void**)&pW2L, d_W2TL);
    cudaGetSymbolAddress((void**)&pM1H, d_M1TH); cudaGetSymbolAddress((void**)&pM1L, d_M1TL);
    cudaGetSymbolAddress((void**)&pM2H, d_M2TH); cudaGetSymbolAddress((void**)&pM2L, d_M2TL);
    cudaGetSymbolAddress((void**)&pPJH, d_PJTH); cudaGetSymbolAddress((void**)&pPJL, d_PJTL);
    cudaGetSymbolAddress((void**)&pXIH, d_XINH); cudaGetSymbolAddress((void**)&pXIL, d_XINL);
    cudaGetSymbolAddress((void**)&pHH, d_HH); cudaGetSymbolAddress((void**)&pHL, d_HL);
    cudaGetSymbolAddress((void**)&pUH, d_UH); cudaGetSymbolAddress((void**)&pUL, d_UL);
    cudaGetSymbolAddress((void**)&pEMB, d_EMB); cudaGetSymbolAddress((void**)&pOUT, d_OUT);
    cudaGetSymbolAddress((void**)&pB2, d_B2P);

    sched_kernel<<<1, 1024>>>();
    detect_kernel<<<1, 32>>>(t_r, x_cat_r);
    convert_t_kernel<<<BATCH / 256, 256>>>(t_r);
    convert_cat_kernel<<<(BATCH * NCAT + 255) / 256, 256>>>(x_cat_r);
    pad_bias_kernel<<<2, 256>>>(mlp_b2);
    temb_kernel<<<dim3(TPAD, DIMT / 256), 256>>>();

    dim3 tb(32, 8);
    transpose_split<<<dim3(DIMT / 32, DIMT / 32), tb>>>(te_w1, DIMT, DIMT, DIMT, pW1H, pW1L);
    transpose_split<<<dim3(DIMT / 32, DIMT / 32), tb>>>(te_w2, DIMT, DIMT, DIMT, pW2H, pW2L);
    transpose_split<<<dim3(DIMT / 32, DIMT / 32), tb>>>(mlp_w1, DIMT, HIDN, DIMT, pM1H, pM1L);
    transpose_split<<<dim3(NPAD2 / 32, HIDN / 32), tb>>>(mlp_w2, HIDN, DIN, HIDN, pM2H, pM2L);
    transpose_split<<<dim3(DIMT / 32, KPAD / 32), tb>>>(proj_w, DIN, DIMT, KPAD, pPJH, pPJL);

    // te MLP over 1024 (padded) unique timesteps
    mma_gemm<<<dim3(DIMT / 128, TPAD / 128), 256, GSMEM_BYTES>>>(
        pE0H, pE0L, pW1H, pW1L, te_b1, nullptr, pE1H, pE1L, nullptr, DIMT, DIMT, /*silu*/2);
    mma_gemm<<<dim3(DIMT / 128, TPAD / 128), 256, GSMEM_BYTES>>>(
        pE1H, pE1L, pW2H, pW2L, te_b2, pEMB, nullptr, nullptr, nullptr, DIMT, DIMT, /*fp32*/0);

    build_xin_kernel<<<BATCH, 128>>>(x_num, noise, gumbel);

    // proj: h = x_in@proj_w + proj_b + emb[t]   -> hi/lo
    mma_gemm<<<dim3(DIMT / 128, BATCH / 128), 256, GSMEM_BYTES>>>(
        pXIH, pXIL, pPJH, pPJL, proj_b, nullptr, pHH, pHL, pEMB, KPAD, DIMT, /*emb*/3);
    // mlp1: relu -> hi/lo
    mma_gemm<<<dim3(HIDN / 128, BATCH / 128), 256, GSMEM_BYTES>>>(
        pHH, pHL, pM1H, pM1L, mlp_b1, nullptr, pUH, pUL, nullptr, DIMT, HIDN, /*relu*/1);
    // mlp2: fp32 out (padded to 512)
    mma_gemm<<<dim3(NPAD2 / 128, BATCH / 128), 256, GSMEM_BYTES>>>(
        pUH, pUL, pM2H, pM2L, pB2, pOUT, nullptr, nullptr, nullptr, HIDN, NPAD2, /*fp32*/0);

    loss_kernel<<<BATCH / 8, 256>>>(noise);
    final_kernel<<<1, 256>>>(out);
}

// round 10
// speedup vs baseline: 10.1070x; 1.0769x over previous
#include <cuda_runtime.h>
#include <cuda_bf16.h>
#include <math.h>
#include <stdint.h>

// ---------------- problem constants ----------------
#define BATCH  16384
#define NNUM   16
#define NCAT   24
#define KCLS   16
#define CATDIM 384
#define DIN    400
#define KPAD   512          // padded DIN for proj GEMM
#define DIMT   1024
#define HIDN   1024
#define NPAD2  512          // padded DIN for mlp2 output
#define TSTEPS 1000
#define TPAD   1024

#define LOGK_F 2.772588722239781f
#define CL_F   (-69.07755278982137f)

// ---------------- device scratch ----------------
__device__ float d_LOG_A[TSTEPS], d_LOG_1M_A[TSTEPS];
__device__ float d_LOG_CA[TSTEPS], d_LOG_1M_CA[TSTEPS];
__device__ float d_SQAC[TSTEPS], d_SQ1MAC[TSTEPS];
__device__ float d_KLP;
__device__ int   d_t64, d_c64;
__device__ int   d_TT[BATCH];
__device__ int   d_CAT[BATCH * NCAT];
__device__ int   d_SAMP[BATCH * NCAT];

__device__ __nv_bfloat16 d_E0H[TPAD * DIMT], d_E0L[TPAD * DIMT];
__device__ __nv_bfloat16 d_E1H[TPAD * DIMT], d_E1L[TPAD * DIMT];
__device__ float         d_EMB[TPAD * DIMT];
__device__ __nv_bfloat16 d_W1TH[DIMT * DIMT], d_W1TL[DIMT * DIMT];   // te_w1^T
__device__ __nv_bfloat16 d_W2TH[DIMT * DIMT], d_W2TL[DIMT * DIMT];   // te_w2^T
__device__ __nv_bfloat16 d_M1TH[HIDN * DIMT], d_M1TL[HIDN * DIMT];   // mlp_w1^T
__device__ __nv_bfloat16 d_M2TH[NPAD2 * HIDN], d_M2TL[NPAD2 * HIDN]; // mlp_w2^T padded
__device__ __nv_bfloat16 d_PJTH[DIMT * KPAD], d_PJTL[DIMT * KPAD];   // proj_w^T padded
__device__ __nv_bfloat16 d_XINH[(size_t)BATCH * KPAD], d_XINL[(size_t)BATCH * KPAD];
__device__ __nv_bfloat16 d_HH[(size_t)BATCH * DIMT], d_HL[(size_t)BATCH * DIMT];
__device__ __nv_bfloat16 d_UH[(size_t)BATCH * DIMT], d_UL[(size_t)BATCH * DIMT];
__device__ float         d_OUT[(size_t)BATCH * NPAD2];
__device__ float         d_B2P[NPAD2];
__device__ float d_PART[BATCH / 8];

// ---------------- helpers ----------------
__device__ __forceinline__ float laddexp(float a, float b) {
    float m = fmaxf(a, b);
    return m + logf(expf(a - m) + expf(b - m));
}
__device__ __forceinline__ uint32_t smem_u32(const void* p) {
    return (uint32_t)__cvta_generic_to_shared(p);
}
#define SWZ128(o) ((o) ^ (((o) >> 3) & 0x70))

__device__ __forceinline__ void ldsm4(uint32_t* r, uint32_t addr) {
    asm volatile("ldmatrix.sync.aligned.m8n8.x4.shared.b16 {%0,%1,%2,%3}, [%4];"
        : "=r"(r[0]), "=r"(r[1]), "=r"(r[2]), "=r"(r[3]) : "r"(addr));
}
__device__ __forceinline__ void mma16816(float* c, const uint32_t* a, uint32_t b0, uint32_t b1) {
    asm volatile("mma.sync.aligned.m16n8k16.row.col.f32.bf16.bf16.f32 "
        "{%0,%1,%2,%3}, {%4,%5,%6,%7}, {%8,%9}, {%0,%1,%2,%3};"
        : "+f"(c[0]), "+f"(c[1]), "+f"(c[2]), "+f"(c[3])
        : "r"(a[0]), "r"(a[1]), "r"(a[2]), "r"(a[3]), "r"(b0), "r"(b1));
}

// ---------------- schedules ----------------
__global__ void sched_kernel() {
    __shared__ double s[1024];
    int i = threadIdx.x;
    const double PI = 3.14159265358979323846;
    double la = 0.0;
    if (i < TSTEPS) {
        double u0 = (double)i / (double)TSTEPS;
        double u1 = (double)(i + 1) / (double)TSTEPS;
        double c0 = cos((u0 + 0.008) / 1.008 * PI / 2.0); double ab0 = c0 * c0;
        double c1 = cos((u1 + 0.008) / 1.008 * PI / 2.0); double ab1 = c1 * c1;
        double beta = 1.0 - ab1 / ab0;
        if (beta > 0.999) beta = 0.999;
        la = log(1.0 - beta);
    }
    s[i] = la;
    __syncthreads();
    #pragma unroll
    for (int off = 1; off < 1024; off <<= 1) {
        double v = (i >= off) ? s[i - off] : 0.0;
        __syncthreads();
        s[i] += v;
        __syncthreads();
    }
    if (i < TSTEPS) {
        double lca = s[i];
        d_LOG_A[i]     = (float)la;
        d_LOG_1M_A[i]  = (float)log(1.0 - exp(la) + 1e-40);
        d_LOG_CA[i]    = (float)lca;
        d_LOG_1M_CA[i] = (float)log(1.0 - exp(lca) + 1e-40);
        double ac = exp(lca);
        d_SQAC[i]   = (float)sqrt(ac);
        d_SQ1MAC[i] = (float)sqrt(1.0 - ac);
    }
    __syncthreads();
    if (i == 0) {
        float lcaT = d_LOG_CA[TSTEPS - 1], l1mT = d_LOG_1M_CA[TSTEPS - 1];
        float hT = laddexp(lcaT, l1mT - LOGK_F);
        float oT = laddexp(CL_F + lcaT, l1mT - LOGK_F);
        d_KLP = (float)NCAT * (expf(hT) * (hT + LOGK_F) + 15.0f * expf(oT) * (oT + LOGK_F));
    }
}

// ---------------- dtype sniff + fused conversions ----------------
__global__ void detect_kernel(const int* __restrict__ traw, const int* __restrict__ craw) {
    if (threadIdx.x != 0) return;
    int z = 1;
    for (int i = 0; i < 64; i++) if (traw[2 * i + 1] != 0) { z = 0; break; }
    d_t64 = z;
    z = 1;
    for (int i = 0; i < 64; i++) if (craw[2 * i + 1] != 0) { z = 0; break; }
    d_c64 = z;
}
__global__ void convert_all_kernel(const int* __restrict__ traw, const int* __restrict__ craw,
                                   const float* __restrict__ b2) {
    int i = blockIdx.x * blockDim.x + threadIdx.x;
    if (i < BATCH) d_TT[i] = d_t64 ? traw[2 * i] : traw[i];
    if (i < BATCH * NCAT) d_CAT[i] = d_c64 ? craw[2 * i] : craw[i];
    if (i < NPAD2) d_B2P[i] = (i < DIN) ? b2[i] : 0.f;
}

// ---------------- timestep embedding (hi/lo bf16, padded rows zero) --------
__global__ void temb_kernel() {
    int t = blockIdx.x;
    int j = blockIdx.y * blockDim.x + threadIdx.x;
    float v = 0.f;
    if (t < TSTEPS) {
        int h = j & 511;
        float freq = expf(-9.210340371976184f * (float)h / 512.0f);
        float arg = (float)t * freq;
        v = (j < 512) ? cosf(arg) : sinf(arg);
    }
    __nv_bfloat16 hi = __float2bfloat16(v);
    __nv_bfloat16 lo = __float2bfloat16(v - __bfloat162float(hi));
    d_E0H[t * DIMT + j] = hi;
    d_E0L[t * DIMT + j] = lo;
}

// ---------------- transpose + hi/lo split: out[c, r] = in[r, c] ----------
__global__ void transpose_split(const float* __restrict__ in, int R, int C,
                                int Rpad, __nv_bfloat16* __restrict__ oh,
                                __nv_bfloat16* __restrict__ ol) {
    __shared__ float tl[32][33];
    int c0 = blockIdx.x * 32, r0 = blockIdx.y * 32;
    #pragma unroll
    for (int k = 0; k < 4; k++) {
        int r = r0 + threadIdx.y + k * 8;
        int c = c0 + threadIdx.x;
        float v = (r < R && c < C) ? in[(size_t)r * C + c] : 0.f;
        tl[threadIdx.x][threadIdx.y + k * 8] = v;
    }
    __syncthreads();
    #pragma unroll
    for (int k = 0; k < 4; k++) {
        int c = c0 + threadIdx.y + k * 8;   // out row
        int r = r0 + threadIdx.x;           // out col
        float v = tl[threadIdx.y + k * 8][threadIdx.x];
        __nv_bfloat16 h = __float2bfloat16(v);
        oh[(size_t)c * Rpad + r] = h;
        ol[(size_t)c * Rpad + r] = __float2bfloat16(v - __bfloat162float(h));
    }
}

// ---------------- build x_in (hi/lo bf16, padded to 512) + sampling -------
__global__ __launch_bounds__(128) void build_xin_kernel(
    const float* __restrict__ x_num, const float* __restrict__ noise,
    const float* __restrict__ gumbel) {
    int b = blockIdx.x;
    int tid = threadIdx.x;
    __shared__ float s_x[NNUM];
    __shared__ int   s_s[NCAT];
    int t = d_TT[b];

    if (tid < NNUM)
        s_x[tid] = d_SQAC[t] * x_num[b * NNUM + tid] + d_SQ1MAC[t] * noise[b * NNUM + tid];
    if (tid < NCAT) {
        int hot = d_CAT[b * NCAT + tid];
        float hv = laddexp(d_LOG_CA[t], d_LOG_1M_CA[t] - LOGK_F);
        float ov = laddexp(CL_F + d_LOG_CA[t], d_LOG_1M_CA[t] - LOGK_F);
        const float* gp = gumbel + (size_t)b * CATDIM + tid * KCLS;
        float best = -1e30f; int bi = 0;
        #pragma unroll
        for (int k = 0; k < KCLS; k++) {
            float g = -logf(-logf(gp[k] + 1e-30f) + 1e-30f);
            float v = g + ((k == hot) ? hv : ov);
            if (v > best) { best = v; bi = k; }
        }
        s_s[tid] = bi;
        d_SAMP[b * NCAT + tid] = bi;
    }
    __syncthreads();

    const __nv_bfloat16 clh = __float2bfloat16(CL_F);
    const __nv_bfloat16 cll = __float2bfloat16(CL_F - __bfloat162float(clh));
    #pragma unroll
    for (int rr = 0; rr < KPAD / 128; rr++) {
        int j = tid + rr * 128;
        __nv_bfloat16 h, l;
        if (j < NNUM) {
            float v = s_x[j];
            h = __float2bfloat16(v);
            l = __float2bfloat16(v - __bfloat162float(h));
        } else if (j < DIN) {
            int c = (j - NNUM) >> 4, k = (j - NNUM) & 15;
            if (k == s_s[c]) { h = __float2bfloat16(0.f); l = h; }
            else { h = clh; l = cll; }
        } else {
            h = __float2bfloat16(0.f); l = h;
        }
        d_XINH[(size_t)b * KPAD + j] = h;
        d_XINL[(size_t)b * KPAD + j] = l;
    }
}

// ---------------- fused 3-term bf16 mma.sync GEMM -------------------------
// D = Ahi@Bhi^T + Ahi@Blo^T + Alo@Bhi^T + bias.  All 4 tiles loaded ONCE per
// 64-wide k-block, 2-stage cp.async, 128x128 CTA tile, 8 warps.
// mode 0: fp32 out   1: relu->hi/lo   2: silu->hi/lo   3: +emb[t[row]]->hi/lo
#define GSMEM_BYTES 131072
__global__ __launch_bounds__(256) void mma_gemm(
    const __nv_bfloat16* __restrict__ Ahi, const __nv_bfloat16* __restrict__ Alo,
    const __nv_bfloat16* __restrict__ Bhi, const __nv_bfloat16* __restrict__ Blo,
    const float* __restrict__ bias,
    float* __restrict__ outF, __nv_bfloat16* __restrict__ outH, __nv_bfloat16* __restrict__ outL,
    const float* __restrict__ emb,
    int Kelem, int ldOut, int mode)
{
    extern __shared__ char smem[];
    const uint32_t sbase = smem_u32(smem);      // per stage 64KB: Ahi|Alo|Bhi|Blo (16KB each)
    int tid = threadIdx.x, wid = tid >> 5, lane = tid & 31;
    int wm = (wid & 3) * 32, wn = (wid >> 2) * 64;
    int rowBase = blockIdx.y * 128, colBase = blockIdx.x * 128;

    int KS = Kelem >> 6;

    // cp.async mapping: per tile 1024 16B-chunks / 256 thr = 4 chunks (same row)
    int c0i = tid * 4;
    int ldRow = c0i >> 3;
    int ldUn  = c0i & 7;           // 0 or 4

    float acc[2][8][4];
    #pragma unroll
    for (int a = 0; a < 2; a++)
        #pragma unroll
        for (int b = 0; b < 8; b++)
            #pragma unroll
            for (int c = 0; c < 4; c++) acc[a][b][c] = 0.f;

    auto issue = [&](int s, int st) {
        int kb = s << 6;
        const __nv_bfloat16* gaH = Ahi + (size_t)(rowBase + ldRow) * Kelem + kb + ldUn * 8;
        const __nv_bfloat16* gaL = Alo + (size_t)(rowBase + ldRow) * Kelem + kb + ldUn * 8;
        const __nv_bfloat16* gbH = Bhi + (size_t)(colBase + ldRow) * Kelem + kb + ldUn * 8;
        const __nv_bfloat16* gbL = Blo + (size_t)(colBase + ldRow) * Kelem + kb + ldUn * 8;
        uint32_t base = sbase + st * 65536;
        #pragma unroll
        for (int q = 0; q < 4; q++) {
            uint32_t off = SWZ128(ldRow * 128 + (ldUn + q) * 16);
            asm volatile("cp.async.cg.shared.global [%0], [%1], 16;" :: "r"(base + off),         "l"(gaH + q * 8));
            asm volatile("cp.async.cg.shared.global [%0], [%1], 16;" :: "r"(base + 16384 + off), "l"(gaL + q * 8));
            asm volatile("cp.async.cg.shared.global [%0], [%1], 16;" :: "r"(base + 32768 + off), "l"(gbH + q * 8));
            asm volatile("cp.async.cg.shared.global [%0], [%1], 16;" :: "r"(base + 49152 + off), "l"(gbL + q * 8));
        }
    };

    issue(0, 0);
    asm volatile("cp.async.commit_group;\n" ::: "memory");

    // ldmatrix per-lane address components
    int aRowC = wm + (lane & 15);
    int aKC   = (lane & 16);            // byte offset (16B = 8 elems)
    int bRowC = wn + (lane & 7) + ((lane & 16) >> 1);
    int bKC   = (lane & 8) * 2;         // byte offset

    for (int s = 0; s < KS; s++) {
        if (s + 1 < KS) issue(s + 1, (s + 1) & 1);
        asm volatile("cp.async.commit_group;\n" ::: "memory");
        asm volatile("cp.async.wait_group 1;\n" ::: "memory");
        __syncthreads();

        uint32_t base = sbase + (s & 1) * 65536;
        uint32_t baAH = base, baAL = base + 16384, baBH = base + 32768, baBL = base + 49152;
        #pragma unroll
        for (int kk = 0; kk < 4; kk++) {
            uint32_t aH[2][4], aL[2][4], bH[4][4], bL[4][4];
            #pragma unroll
            for (int mi = 0; mi < 2; mi++) {
                uint32_t off = SWZ128((aRowC + mi * 16) * 128 + kk * 32 + aKC);
                ldsm4(aH[mi], baAH + off);
            }
            #pragma unroll
            for (int nt = 0; nt < 4; nt++) {
                uint32_t off = SWZ128((bRowC + nt * 16) * 128 + kk * 32 + bKC);
                ldsm4(bH[nt], baBH + off);
            }
            // term 1: Ahi * Bhi
            #pragma unroll
            for (int mi = 0; mi < 2; mi++)
                #pragma unroll
                for (int nt = 0; nt < 4; nt++) {
                    mma16816(acc[mi][nt * 2],     aH[mi], bH[nt][0], bH[nt][1]);
                    mma16816(acc[mi][nt * 2 + 1], aH[mi], bH[nt][2], bH[nt][3]);
                }
            // term 2: Ahi * Blo
            #pragma unroll
            for (int nt = 0; nt < 4; nt++) {
                uint32_t off = SWZ128((bRowC + nt * 16) * 128 + kk * 32 + bKC);
                ldsm4(bL[nt], baBL + off);
            }
            #pragma unroll
            for (int mi = 0; mi < 2; mi++)
                #pragma unroll
                for (int nt = 0; nt < 4; nt++) {
                    mma16816(acc[mi][nt * 2],     aH[mi], bL[nt][0], bL[nt][1]);
                    mma16816(acc[mi][nt * 2 + 1], aH[mi], bL[nt][2], bL[nt][3]);
                }
            // term 3: Alo * Bhi
            #pragma unroll
            for (int mi = 0; mi < 2; mi++) {
                uint32_t off = SWZ128((aRowC + mi * 16) * 128 + kk * 32 + aKC);
                ldsm4(aL[mi], baAL + off);
            }
            #pragma unroll
            for (int mi = 0; mi < 2; mi++)
                #pragma unroll
                for (int nt = 0; nt < 4; nt++) {
                    mma16816(acc[mi][nt * 2],     aL[mi], bH[nt][0], bH[nt][1]);
                    mma16816(acc[mi][nt * 2 + 1], aL[mi], bH[nt][2], bH[nt][3]);
                }
        }
        __syncthreads();
    }

    // ---------------- epilogue ----------------
    #pragma unroll
    for (int mi = 0; mi < 2; mi++) {
        #pragma unroll
        for (int half = 0; half < 2; half++) {
            int r = rowBase + wm + mi * 16 + (lane >> 2) + half * 8;
            int tE = (mode == 3) ? d_TT[r] : 0;
            #pragma unroll
            for (int ni = 0; ni < 8; ni++) {
                int c = colBase + wn + ni * 8 + (lane & 3) * 2;
                float v0 = acc[mi][ni][half * 2 + 0] + bias[c];
                float v1 = acc[mi][ni][half * 2 + 1] + bias[c + 1];
                if (mode == 0) {
                    float2 v; v.x = v0; v.y = v1;
                    *reinterpret_cast<float2*>(&outF[(size_t)r * ldOut + c]) = v;
                } else {
                    if (mode == 1) {
                        v0 = fmaxf(v0, 0.f); v1 = fmaxf(v1, 0.f);
                    } else if (mode == 2) {
                        v0 = v0 / (1.f + expf(-v0)); v1 = v1 / (1.f + expf(-v1));
                    } else {
                        v0 += emb[(size_t)tE * DIMT + c];
                        v1 += emb[(size_t)tE * DIMT + c + 1];
                    }
                    __nv_bfloat16 h0 = __float2bfloat16(v0), h1 = __float2bfloat16(v1);
                    __nv_bfloat162 hh, ll;
                    hh.x = h0; hh.y = h1;
                    ll.x = __float2bfloat16(v0 - __bfloat162float(h0));
                    ll.y = __float2bfloat16(v1 - __bfloat162float(h1));
                    *reinterpret_cast<__nv_bfloat162*>(&outH[(size_t)r * ldOut + c]) = hh;
                    *reinterpret_cast<__nv_bfloat162*>(&outL[(size_t)r * ldOut + c]) = ll;
                }
            }
        }
    }
}

// ---------------- per-row loss (OUT stride = NPAD2) -----------------------
__global__ __launch_bounds__(256) void loss_kernel(const float* __restrict__ noise) {
    int warp = threadIdx.x >> 5, lane = threadIdx.x & 31;
    int b = blockIdx.x * 8 + warp;
    __shared__ float s_row[8];
    int t = d_TT[b];
    int tm1 = (t > 0) ? t - 1 : 0;
    const float* outp = d_OUT + (size_t)b * NPAD2;

    float g = 0.f;
    if (lane < NNUM) { float d = noise[b * NNUM + lane] - outp[lane]; g = d * d; }

    float kl = 0.f, dec = 0.f;
    if (lane < NCAT) {
        int hot = d_CAT[b * NCAT + lane];
        int sm  = d_SAMP[b * NCAT + lane];
        const float* oc = outp + NNUM + lane * KCLS;
        float v[KCLS];
        float mx = -1e30f;
        #pragma unroll
        for (int k = 0; k < KCLS; k++) { v[k] = oc[k]; mx = fmaxf(mx, v[k]); }
        float se = 0.f;
        #pragma unroll
        for (int k = 0; k < KCLS; k++) se += expf(v[k] - mx);
        float lse = mx + logf(se);

        float PH = laddexp(d_LOG_A[t], d_LOG_1M_A[t] - LOGK_F);
        float PO = laddexp(CL_F + d_LOG_A[t], d_LOG_1M_A[t] - LOGK_F);
        float H1, O1;
        if (t == 0) { H1 = 0.f; O1 = CL_F; }
        else {
            H1 = laddexp(d_LOG_CA[tm1], d_LOG_1M_CA[tm1] - LOGK_F);
            O1 = laddexp(CL_F + d_LOG_CA[tm1], d_LOG_1M_CA[tm1] - LOGK_F);
        }

        float unm[KCLS], unt[KCLS];
        float mmax = -1e30f, tmax = -1e30f;
        #pragma unroll
        for (int k = 0; k < KCLS; k++) {
            float lx0 = v[k] - lse;
            float ev  = (t == 0) ? lx0
                                 : laddexp(lx0 + d_LOG_CA[tm1], d_LOG_1M_CA[tm1] - LOGK_F);
            float pk  = (k == sm) ? PH : PO;
            float um = ev + pk;            unm[k] = um; mmax = fmaxf(mmax, um);
            float ut = ((k == hot) ? H1 : O1) + pk; unt[k] = ut; tmax = fmaxf(tmax, ut);
        }
        float ms = 0.f, ts = 0.f;
        #pragma unroll
        for (int k = 0; k < KCLS; k++) { ms += expf(unm[k] - mmax); ts += expf(unt[k] - tmax); }
        float mlse = mmax + logf(ms), tlse = tmax + logf(ts);
        float EXPL = expf(CL_F);
        #pragma unroll
        for (int k = 0; k < KCLS; k++) {
            float lt = unt[k] - tlse, lm = unm[k] - mlse;
            kl  += expf(lt) * (lt - lm);
            dec -= ((k == hot) ? 1.0f : EXPL) * lm;
        }
    }

    #pragma unroll
    for (int o = 16; o; o >>= 1) {
        g   += __shfl_xor_sync(0xffffffffu, g, o);
        kl  += __shfl_xor_sync(0xffffffffu, kl, o);
        dec += __shfl_xor_sync(0xffffffffu, dec, o);
    }
    if (lane == 0) {
        float Lt = (t == 0) ? dec : kl;
        s_row[warp] = (Lt + d_KLP) * (1.0f / ((float)NCAT * (float)BATCH))
                    + g * (1.0f / ((float)NNUM * (float)BATCH));
    }
    __syncthreads();
    if (threadIdx.x == 0) {
        float s = 0.f;
        #pragma unroll
        for (int i = 0; i < 8; i++) s += s_row[i];
        d_PART[blockIdx.x] = s;
    }
}

__global__ void final_kernel(float* __restrict__ out) {
    __shared__ float s[256];
    float a = 0.f;
    for (int i = threadIdx.x; i < BATCH / 8; i += 256) a += d_PART[i];
    s[threadIdx.x] = a;
    __syncthreads();
    for (int st = 128; st; st >>= 1) {
        if (threadIdx.x < st) s[threadIdx.x] += s[threadIdx.x + st];
        __syncthreads();
    }
    if (threadIdx.x == 0) out[0] = s[0];
}

// ---------------- launch ----------------
extern "C" void kernel_launch(void* const* d_in, const int* in_sizes, int n_in,
                              void* d_out, int out_size) {
    const float* x_num   = (const float*)d_in[0];
    const int*   x_cat_r = (const int*)  d_in[1];
    const int*   t_r     = (const int*)  d_in[2];
    const float* noise   = (const float*)d_in[3];
    const float* gumbel  = (const float*)d_in[4];
    const float* te_w1   = (const float*)d_in[5];
    const float* te_b1   = (const float*)d_in[6];
    const float* te_w2   = (const float*)d_in[7];
    const float* te_b2   = (const float*)d_in[8];
    const float* proj_w  = (const float*)d_in[9];
    const float* proj_b  = (const float*)d_in[10];
    const float* mlp_w1  = (const float*)d_in[11];
    const float* mlp_b1  = (const float*)d_in[12];
    const float* mlp_w2  = (const float*)d_in[13];
    const float* mlp_b2  = (const float*)d_in[14];
    float* out = (float*)d_out;

    cudaFuncSetAttribute(mma_gemm, cudaFuncAttributeMaxDynamicSharedMemorySize, GSMEM_BYTES);

    __nv_bfloat16 *pE0H, *pE0L, *pE1H, *pE1L;
    __nv_bfloat16 *pW1H, *pW1L, *pW2H, *pW2L, *pM1H, *pM1L, *pM2H, *pM2L, *pPJH, *pPJL;
    __nv_bfloat16 *pXIH, *pXIL, *pHH, *pHL, *pUH, *pUL;
    float *pEMB, *pOUT, *pB2;
    cudaGetSymbolAddress((void**)&pE0H, d_E0H); cudaGetSymbolAddress((void**)&pE0L, d_E0L);
    cudaGetSymbolAddress((void**)&pE1H, d_E1H); cudaGetSymbolAddress((void**)&pE1L, d_E1L);
    cudaGetSymbolAddress((void**)&pW1H, d_W1TH); cudaGetSymbolAddress((void**)&pW1L, d_W1TL);
    cudaGetSymbolAddress((void**)&pW2H, d_W2TH); cudaGetSymbolAddress((void**)&pW2L, d_W2TL);
    cudaGetSymbolAddress((void**)&pM1H, d_M1TH); cudaGetSymbolAddress((void**)&pM1L, d_M1TL);
    cudaGetSymbolAddress((void**)&pM2H, d_M2TH); cudaGetSymbolAddress((void**)&pM2L, d_M2TL);
    cudaGetSymbolAddress((void**)&pPJH, d_PJTH); cudaGetSymbolAddress((void**)&pPJL, d_PJTL);
    cudaGetSymbolAddress((void**)&pXIH, d_XINH); cudaGetSymbolAddress((void**)&pXIL, d_XINL);
    cudaGetSymbolAddress((void**)&pHH, d_HH); cudaGetSymbolAddress((void**)&pHL, d_HL);
    cudaGetSymbolAddress((void**)&pUH, d_UH); cudaGetSymbolAddress((void**)&pUL, d_UL);
    cudaGetSymbolAddress((void**)&pEMB, d_EMB); cudaGetSymbolAddress((void**)&pOUT, d_OUT);
    cudaGetSymbolAddress((void**)&pB2, d_B2P);

    sched_kernel<<<1, 1024>>>();
    detect_kernel<<<1, 32>>>(t_r, x_cat_r);
    convert_all_kernel<<<(BATCH * NCAT + 255) / 256, 256>>>(t_r, x_cat_r, mlp_b2);
    temb_kernel<<<dim3(TPAD, DIMT / 256), 256>>>();

    dim3 tb(32, 8);
    transpose_split<<<dim3(DIMT / 32, DIMT / 32), tb>>>(te_w1, DIMT, DIMT, DIMT, pW1H, pW1L);
    transpose_split<<<dim3(DIMT / 32, DIMT / 32), tb>>>(te_w2, DIMT, DIMT, DIMT, pW2H, pW2L);
    transpose_split<<<dim3(DIMT / 32, DIMT / 32), tb>>>(mlp_w1, DIMT, HIDN, DIMT, pM1H, pM1L);
    transpose_split<<<dim3(NPAD2 / 32, HIDN / 32), tb>>>(mlp_w2, HIDN, DIN, HIDN, pM2H, pM2L);
    transpose_split<<<dim3(DIMT / 32, KPAD / 32), tb>>>(proj_w, DIN, DIMT, KPAD, pPJH, pPJL);

    // te MLP over 1024 (padded) unique timesteps
    mma_gemm<<<dim3(DIMT / 128, TPAD / 128), 256, GSMEM_BYTES>>>(
        pE0H, pE0L, pW1H, pW1L, te_b1, nullptr, pE1H, pE1L, nullptr, DIMT, DIMT, /*silu*/2);
    mma_gemm<<<dim3(DIMT / 128, TPAD / 128), 256, GSMEM_BYTES>>>(
        pE1H, pE1L, pW2H, pW2L, te_b2, pEMB, nullptr, nullptr, nullptr, DIMT, DIMT, /*fp32*/0);

    build_xin_kernel<<<BATCH, 128>>>(x_num, noise, gumbel);

    // proj: h = x_in@proj_w + proj_b + emb[t]   -> hi/lo
    mma_gemm<<<dim3(DIMT / 128, BATCH / 128), 256, GSMEM_BYTES>>>(
        pXIH, pXIL, pPJH, pPJL, proj_b, nullptr, pHH, pHL, pEMB, KPAD, DIMT, /*emb*/3);
    // mlp1: relu -> hi/lo
    mma_gemm<<<dim3(HIDN / 128, BATCH / 128), 256, GSMEM_BYTES>>>(
        pHH, pHL, pM1H, pM1L, mlp_b1, nullptr, pUH, pUL, nullptr, DIMT, HIDN, /*relu*/1);
    // mlp2: fp32 out (padded to 512)
    mma_gemm<<<dim3(NPAD2 / 128, BATCH / 128), 256, GSMEM_BYTES>>>(
        pUH, pUL, pM2H, pM2L, pB2, pOUT, nullptr, nullptr, nullptr, HIDN, NPAD2, /*fp32*/0);

    loss_kernel<<<BATCH / 8, 256>>>(noise);
    final_kernel<<<1, 256>>>(out);
}

// round 11
// speedup vs baseline: 10.2394x; 1.0131x over previous
#include <cuda_runtime.h>
#include <cuda_bf16.h>
#include <math.h>
#include <stdint.h>

// ---------------- problem constants ----------------
#define BATCH  16384
#define NNUM   16
#define NCAT   24
#define KCLS   16
#define CATDIM 384
#define DIN    400
#define KPAD   512          // padded DIN for proj GEMM
#define DIMT   1024
#define HIDN   1024
#define NPAD2  512          // padded DIN for mlp2 output
#define TSTEPS 1000
#define TPAD   1024

#define LOGK_F 2.772588722239781f
#define CL_F   (-69.07755278982137f)

// ---------------- device scratch ----------------
__device__ float d_LOG_A[TSTEPS], d_LOG_1M_A[TSTEPS];
__device__ float d_LOG_CA[TSTEPS], d_LOG_1M_CA[TSTEPS];
__device__ float d_SQAC[TSTEPS], d_SQ1MAC[TSTEPS];
__device__ float d_KLP;
__device__ int   d_t64, d_c64;
__device__ int   d_TT[BATCH];
__device__ int   d_CAT[BATCH * NCAT];
__device__ int   d_SAMP[BATCH * NCAT];

__device__ __nv_bfloat16 d_E0H[TPAD * DIMT], d_E0L[TPAD * DIMT];
__device__ __nv_bfloat16 d_E1H[TPAD * DIMT], d_E1L[TPAD * DIMT];
__device__ float         d_EMB[TPAD * DIMT];
__device__ __nv_bfloat16 d_W1TH[DIMT * DIMT], d_W1TL[DIMT * DIMT];   // te_w1^T
__device__ __nv_bfloat16 d_W2TH[DIMT * DIMT], d_W2TL[DIMT * DIMT];   // te_w2^T
__device__ __nv_bfloat16 d_M1TH[HIDN * DIMT], d_M1TL[HIDN * DIMT];   // mlp_w1^T
__device__ __nv_bfloat16 d_M2TH[NPAD2 * HIDN], d_M2TL[NPAD2 * HIDN]; // mlp_w2^T padded
__device__ __nv_bfloat16 d_PJTH[DIMT * KPAD], d_PJTL[DIMT * KPAD];   // proj_w^T padded
__device__ __nv_bfloat16 d_XINH[(size_t)BATCH * KPAD], d_XINL[(size_t)BATCH * KPAD];
__device__ __nv_bfloat16 d_HH[(size_t)BATCH * DIMT], d_HL[(size_t)BATCH * DIMT];
__device__ __nv_bfloat16 d_UH[(size_t)BATCH * DIMT], d_UL[(size_t)BATCH * DIMT];
__device__ float         d_OUT[(size_t)BATCH * NPAD2];
__device__ float         d_B2P[NPAD2];
__device__ float d_PART[BATCH / 8];

// ---------------- helpers ----------------
__device__ __forceinline__ float laddexp(float a, float b) {
    float m = fmaxf(a, b);
    return m + logf(expf(a - m) + expf(b - m));
}
__device__ __forceinline__ uint32_t smem_u32(const void* p) {
    return (uint32_t)__cvta_generic_to_shared(p);
}
#define SWZ128(o) ((o) ^ (((o) >> 3) & 0x70))

__device__ __forceinline__ void ldsm4(uint32_t* r, uint32_t addr) {
    asm volatile("ldmatrix.sync.aligned.m8n8.x4.shared.b16 {%0,%1,%2,%3}, [%4];"
        : "=r"(r[0]), "=r"(r[1]), "=r"(r[2]), "=r"(r[3]) : "r"(addr));
}
__device__ __forceinline__ void mma16816(float* c, const uint32_t* a, uint32_t b0, uint32_t b1) {
    asm volatile("mma.sync.aligned.m16n8k16.row.col.f32.bf16.bf16.f32 "
        "{%0,%1,%2,%3}, {%4,%5,%6,%7}, {%8,%9}, {%0,%1,%2,%3};"
        : "+f"(c[0]), "+f"(c[1]), "+f"(c[2]), "+f"(c[3])
        : "r"(a[0]), "r"(a[1]), "r"(a[2]), "r"(a[3]), "r"(b0), "r"(b1));
}

// ---------------- schedules ----------------
__global__ void sched_kernel() {
    __shared__ double s[1024];
    int i = threadIdx.x;
    const double PI = 3.14159265358979323846;
    double la = 0.0;
    if (i < TSTEPS) {
        double u0 = (double)i / (double)TSTEPS;
        double u1 = (double)(i + 1) / (double)TSTEPS;
        double c0 = cos((u0 + 0.008) / 1.008 * PI / 2.0); double ab0 = c0 * c0;
        double c1 = cos((u1 + 0.008) / 1.008 * PI / 2.0); double ab1 = c1 * c1;
        double beta = 1.0 - ab1 / ab0;
        if (beta > 0.999) beta = 0.999;
        la = log(1.0 - beta);
    }
    s[i] = la;
    __syncthreads();
    #pragma unroll
    for (int off = 1; off < 1024; off <<= 1) {
        double v = (i >= off) ? s[i - off] : 0.0;
        __syncthreads();
        s[i] += v;
        __syncthreads();
    }
    if (i < TSTEPS) {
        double lca = s[i];
        d_LOG_A[i]     = (float)la;
        d_LOG_1M_A[i]  = (float)log(1.0 - exp(la) + 1e-40);
        d_LOG_CA[i]    = (float)lca;
        d_LOG_1M_CA[i] = (float)log(1.0 - exp(lca) + 1e-40);
        double ac = exp(lca);
        d_SQAC[i]   = (float)sqrt(ac);
        d_SQ1MAC[i] = (float)sqrt(1.0 - ac);
    }
    __syncthreads();
    if (i == 0) {
        float lcaT = d_LOG_CA[TSTEPS - 1], l1mT = d_LOG_1M_CA[TSTEPS - 1];
        float hT = laddexp(lcaT, l1mT - LOGK_F);
        float oT = laddexp(CL_F + lcaT, l1mT - LOGK_F);
        d_KLP = (float)NCAT * (expf(hT) * (hT + LOGK_F) + 15.0f * expf(oT) * (oT + LOGK_F));
    }
}

// ---------------- dtype sniff + fused conversions ----------------
__global__ void detect_kernel(const int* __restrict__ traw, const int* __restrict__ craw) {
    if (threadIdx.x != 0) return;
    int z = 1;
    for (int i = 0; i < 64; i++) if (traw[2 * i + 1] != 0) { z = 0; break; }
    d_t64 = z;
    z = 1;
    for (int i = 0; i < 64; i++) if (craw[2 * i + 1] != 0) { z = 0; break; }
    d_c64 = z;
}
__global__ void convert_all_kernel(const int* __restrict__ traw, const int* __restrict__ craw,
                                   const float* __restrict__ b2) {
    int i = blockIdx.x * blockDim.x + threadIdx.x;
    if (i < BATCH) d_TT[i] = d_t64 ? traw[2 * i] : traw[i];
    if (i < BATCH * NCAT) d_CAT[i] = d_c64 ? craw[2 * i] : craw[i];
    if (i < NPAD2) d_B2P[i] = (i < DIN) ? b2[i] : 0.f;
}

// ---------------- timestep embedding (hi/lo bf16, padded rows zero) --------
__global__ void temb_kernel() {
    int t = blockIdx.x;
    int j = blockIdx.y * blockDim.x + threadIdx.x;
    float v = 0.f;
    if (t < TSTEPS) {
        int h = j & 511;
        float freq = expf(-9.210340371976184f * (float)h / 512.0f);
        float arg = (float)t * freq;
        v = (j < 512) ? cosf(arg) : sinf(arg);
    }
    __nv_bfloat16 hi = __float2bfloat16(v);
    __nv_bfloat16 lo = __float2bfloat16(v - __bfloat162float(hi));
    d_E0H[t * DIMT + j] = hi;
    d_E0L[t * DIMT + j] = lo;
}

// ---------------- ALL weight transposes in one launch ----------------------
__device__ __forceinline__ void do_transpose(
    const float* __restrict__ in, int R, int C, int Rpad,
    __nv_bfloat16* __restrict__ oh, __nv_bfloat16* __restrict__ ol,
    int bx, int by)
{
    __shared__ float tl[32][33];
    int c0 = bx * 32, r0 = by * 32;
    #pragma unroll
    for (int k = 0; k < 4; k++) {
        int r = r0 + threadIdx.y + k * 8;
        int c = c0 + threadIdx.x;
        float v = (r < R && c < C) ? in[(size_t)r * C + c] : 0.f;
        tl[threadIdx.x][threadIdx.y + k * 8] = v;
    }
    __syncthreads();
    #pragma unroll
    for (int k = 0; k < 4; k++) {
        int c = c0 + threadIdx.y + k * 8;   // out row
        int r = r0 + threadIdx.x;           // out col
        float v = tl[threadIdx.y + k * 8][threadIdx.x];
        __nv_bfloat16 h = __float2bfloat16(v);
        oh[(size_t)c * Rpad + r] = h;
        ol[(size_t)c * Rpad + r] = __float2bfloat16(v - __bfloat162float(h));
    }
}

__global__ void transpose_all_kernel(
    const float* __restrict__ te_w1, const float* __restrict__ te_w2,
    const float* __restrict__ mlp_w1, const float* __restrict__ mlp_w2,
    const float* __restrict__ proj_w)
{
    __nv_bfloat16 *pW1H, *pW1L, *pW2H, *pW2L, *pM1H, *pM1L, *pM2H, *pM2L, *pPJH, *pPJL;
    pW1H = d_W1TH; pW1L = d_W1TL; pW2H = d_W2TH; pW2L = d_W2TL;
    pM1H = d_M1TH; pM1L = d_M1TL; pM2H = d_M2TH; pM2L = d_M2TL;
    pPJH = d_PJTH; pPJL = d_PJTL;
    int b = blockIdx.x;
    if (b < 1024) {
        do_transpose(te_w1, DIMT, DIMT, DIMT, pW1H, pW1L, b & 31, b >> 5);
    } else if (b < 2048) {
        b -= 1024;
        do_transpose(te_w2, DIMT, DIMT, DIMT, pW2H, pW2L, b & 31, b >> 5);
    } else if (b < 3072) {
        b -= 2048;
        do_transpose(mlp_w1, DIMT, HIDN, DIMT, pM1H, pM1L, b & 31, b >> 5);
    } else if (b < 3584) {
        b -= 3072;                               // 16 x 32 blocks
        do_transpose(mlp_w2, HIDN, DIN, HIDN, pM2H, pM2L, b & 15, b >> 4);
    } else {
        b -= 3584;                               // 32 x 16 blocks
        do_transpose(proj_w, DIN, DIMT, KPAD, pPJH, pPJL, b & 31, b >> 5);
    }
}

// ---------------- build x_in (hi/lo bf16, padded to 512) + sampling -------
__global__ __launch_bounds__(128) void build_xin_kernel(
    const float* __restrict__ x_num, const float* __restrict__ noise,
    const float* __restrict__ gumbel) {
    int b = blockIdx.x;
    int tid = threadIdx.x;
    __shared__ float s_x[NNUM];
    __shared__ int   s_s[NCAT];
    int t = d_TT[b];

    if (tid < NNUM)
        s_x[tid] = d_SQAC[t] * x_num[b * NNUM + tid] + d_SQ1MAC[t] * noise[b * NNUM + tid];
    if (tid < NCAT) {
        int hot = d_CAT[b * NCAT + tid];
        float hv = laddexp(d_LOG_CA[t], d_LOG_1M_CA[t] - LOGK_F);
        float ov = laddexp(CL_F + d_LOG_CA[t], d_LOG_1M_CA[t] - LOGK_F);
        const float* gp = gumbel + (size_t)b * CATDIM + tid * KCLS;
        float best = -1e30f; int bi = 0;
        #pragma unroll
        for (int k = 0; k < KCLS; k++) {
            float g = -logf(-logf(gp[k] + 1e-30f) + 1e-30f);
            float v = g + ((k == hot) ? hv : ov);
            if (v > best) { best = v; bi = k; }
        }
        s_s[tid] = bi;
        d_SAMP[b * NCAT + tid] = bi;
    }
    __syncthreads();

    const __nv_bfloat16 clh = __float2bfloat16(CL_F);
    const __nv_bfloat16 cll = __float2bfloat16(CL_F - __bfloat162float(clh));
    #pragma unroll
    for (int rr = 0; rr < KPAD / 128; rr++) {
        int j = tid + rr * 128;
        __nv_bfloat16 h, l;
        if (j < NNUM) {
            float v = s_x[j];
            h = __float2bfloat16(v);
            l = __float2bfloat16(v - __bfloat162float(h));
        } else if (j < DIN) {
            int c = (j - NNUM) >> 4, k = (j - NNUM) & 15;
            if (k == s_s[c]) { h = __float2bfloat16(0.f); l = h; }
            else { h = clh; l = cll; }
        } else {
            h = __float2bfloat16(0.f); l = h;
        }
        d_XINH[(size_t)b * KPAD + j] = h;
        d_XINL[(size_t)b * KPAD + j] = l;
    }
}

// ---------------- fused 3-term bf16 mma.sync GEMM, 3-stage pipeline -------
// D = Ahi@Bhi^T + Ahi@Blo^T + Alo@Bhi^T + bias.  4 tiles loaded once per
// 64-wide k-block; 3-stage cp.async (prefetch depth 2); ONE sync per slab.
// mode 0: fp32 out   1: relu->hi/lo   2: silu->hi/lo   3: +emb[t[row]]->hi/lo
#define GSMEM_BYTES 196608
__global__ __launch_bounds__(256) void mma_gemm(
    const __nv_bfloat16* __restrict__ Ahi, const __nv_bfloat16* __restrict__ Alo,
    const __nv_bfloat16* __restrict__ Bhi, const __nv_bfloat16* __restrict__ Blo,
    const float* __restrict__ bias,
    float* __restrict__ outF, __nv_bfloat16* __restrict__ outH, __nv_bfloat16* __restrict__ outL,
    const float* __restrict__ emb,
    int Kelem, int ldOut, int mode)
{
    extern __shared__ char smem[];
    const uint32_t sbase = smem_u32(smem);      // 3 stages x 64KB: Ahi|Alo|Bhi|Blo (16KB each)
    int tid = threadIdx.x, wid = tid >> 5, lane = tid & 31;
    int wm = (wid & 3) * 32, wn = (wid >> 2) * 64;
    int rowBase = blockIdx.y * 128, colBase = blockIdx.x * 128;

    int KS = Kelem >> 6;

    // cp.async mapping: per tile 1024 16B-chunks / 256 thr = 4 chunks (same row)
    int c0i = tid * 4;
    int ldRow = c0i >> 3;
    int ldUn  = c0i & 7;           // 0 or 4

    float acc[2][8][4];
    #pragma unroll
    for (int a = 0; a < 2; a++)
        #pragma unroll
        for (int b = 0; b < 8; b++)
            #pragma unroll
            for (int c = 0; c < 4; c++) acc[a][b][c] = 0.f;

    auto issue = [&](int s) {
        int kb = s << 6;
        int st = s % 3;
        const __nv_bfloat16* gaH = Ahi + (size_t)(rowBase + ldRow) * Kelem + kb + ldUn * 8;
        const __nv_bfloat16* gaL = Alo + (size_t)(rowBase + ldRow) * Kelem + kb + ldUn * 8;
        const __nv_bfloat16* gbH = Bhi + (size_t)(colBase + ldRow) * Kelem + kb + ldUn * 8;
        const __nv_bfloat16* gbL = Blo + (size_t)(colBase + ldRow) * Kelem + kb + ldUn * 8;
        uint32_t base = sbase + st * 65536;
        #pragma unroll
        for (int q = 0; q < 4; q++) {
            uint32_t off = SWZ128(ldRow * 128 + (ldUn + q) * 16);
            asm volatile("cp.async.cg.shared.global [%0], [%1], 16;" :: "r"(base + off),         "l"(gaH + q * 8));
            asm volatile("cp.async.cg.shared.global [%0], [%1], 16;" :: "r"(base + 16384 + off), "l"(gaL + q * 8));
            asm volatile("cp.async.cg.shared.global [%0], [%1], 16;" :: "r"(base + 32768 + off), "l"(gbH + q * 8));
            asm volatile("cp.async.cg.shared.global [%0], [%1], 16;" :: "r"(base + 49152 + off), "l"(gbL + q * 8));
        }
    };

    issue(0);
    asm volatile("cp.async.commit_group;\n" ::: "memory");
    if (KS > 1) issue(1);
    asm volatile("cp.async.commit_group;\n" ::: "memory");

    // ldmatrix per-lane address components
    int aRowC = wm + (lane & 15);
    int aKC   = (lane & 16);            // byte offset (16B = 8 elems)
    int bRowC = wn + (lane & 7) + ((lane & 16) >> 1);
    int bKC   = (lane & 8) * 2;         // byte offset

    for (int s = 0; s < KS; s++) {
        asm volatile("cp.async.wait_group 1;\n" ::: "memory");
        __syncthreads();     // stage s ready; also guarantees stage s-1 compute done chipwide

        // prefetch stage s+2 into the buffer freed by stage s-1
        if (s + 2 < KS) issue(s + 2);
        asm volatile("cp.async.commit_group;\n" ::: "memory");

        uint32_t base = sbase + (s % 3) * 65536;
        uint32_t baAH = base, baAL = base + 16384, baBH = base + 32768, baBL = base + 49152;
        #pragma unroll
        for (int kk = 0; kk < 4; kk++) {
            uint32_t aH[2][4], aL[2][4], bH[4][4], bL[4][4];
            // batch ALL fragment loads first (ptxas overlaps LDSM with HMMA)
            #pragma unroll
            for (int mi = 0; mi < 2; mi++) {
                uint32_t off = SWZ128((aRowC + mi * 16) * 128 + kk * 32 + aKC);
                ldsm4(aH[mi], baAH + off);
                ldsm4(aL[mi], baAL + off);
            }
            #pragma unroll
            for (int nt = 0; nt < 4; nt++) {
                uint32_t off = SWZ128((bRowC + nt * 16) * 128 + kk * 32 + bKC);
                ldsm4(bH[nt], baBH + off);
                ldsm4(bL[nt], baBL + off);
            }
            #pragma unroll
            for (int mi = 0; mi < 2; mi++)
                #pragma unroll
                for (int nt = 0; nt < 4; nt++) {
                    mma16816(acc[mi][nt * 2],     aH[mi], bH[nt][0], bH[nt][1]);
                    mma16816(acc[mi][nt * 2 + 1], aH[mi], bH[nt][2], bH[nt][3]);
                }
            #pragma unroll
            for (int mi = 0; mi < 2; mi++)
                #pragma unroll
                for (int nt = 0; nt < 4; nt++) {
                    mma16816(acc[mi][nt * 2],     aH[mi], bL[nt][0], bL[nt][1]);
                    mma16816(acc[mi][nt * 2 + 1], aH[mi], bL[nt][2], bL[nt][3]);
                }
            #pragma unroll
            for (int mi = 0; mi < 2; mi++)
                #pragma unroll
                for (int nt = 0; nt < 4; nt++) {
                    mma16816(acc[mi][nt * 2],     aL[mi], bH[nt][0], bH[nt][1]);
                    mma16816(acc[mi][nt * 2 + 1], aL[mi], bH[nt][2], bH[nt][3]);
                }
        }
    }

    // ---------------- epilogue ----------------
    #pragma unroll
    for (int mi = 0; mi < 2; mi++) {
        #pragma unroll
        for (int half = 0; half < 2; half++) {
            int r = rowBase + wm + mi * 16 + (lane >> 2) + half * 8;
            int tE = (mode == 3) ? d_TT[r] : 0;
            #pragma unroll
            for (int ni = 0; ni < 8; ni++) {
                int c = colBase + wn + ni * 8 + (lane & 3) * 2;
                float v0 = acc[mi][ni][half * 2 + 0] + bias[c];
                float v1 = acc[mi][ni][half * 2 + 1] + bias[c + 1];
                if (mode == 0) {
                    float2 v; v.x = v0; v.y = v1;
                    *reinterpret_cast<float2*>(&outF[(size_t)r * ldOut + c]) = v;
                } else {
                    if (mode == 1) {
                        v0 = fmaxf(v0, 0.f); v1 = fmaxf(v1, 0.f);
                    } else if (mode == 2) {
                        v0 = v0 / (1.f + expf(-v0)); v1 = v1 / (1.f + expf(-v1));
                    } else {
                        v0 += emb[(size_t)tE * DIMT + c];
                        v1 += emb[(size_t)tE * DIMT + c + 1];
                    }
                    __nv_bfloat16 h0 = __float2bfloat16(v0), h1 = __float2bfloat16(v1);
                    __nv_bfloat162 hh, ll;
                    hh.x = h0; hh.y = h1;
                    ll.x = __float2bfloat16(v0 - __bfloat162float(h0));
                    ll.y = __float2bfloat16(v1 - __bfloat162float(h1));
                    *reinterpret_cast<__nv_bfloat162*>(&outH[(size_t)r * ldOut + c]) = hh;
                    *reinterpret_cast<__nv_bfloat162*>(&outL[(size_t)r * ldOut + c]) = ll;
                }
            }
        }
    }
}

// ---------------- per-row loss (OUT stride = NPAD2) -----------------------
__global__ __launch_bounds__(256) void loss_kernel(const float* __restrict__ noise) {
    int warp = threadIdx.x >> 5, lane = threadIdx.x & 31;
    int b = blockIdx.x * 8 + warp;
    __shared__ float s_row[8];
    int t = d_TT[b];
    int tm1 = (t > 0) ? t - 1 : 0;
    const float* outp = d_OUT + (size_t)b * NPAD2;

    float g = 0.f;
    if (lane < NNUM) { float d = noise[b * NNUM + lane] - outp[lane]; g = d * d; }

    float kl = 0.f, dec = 0.f;
    if (lane < NCAT) {
        int hot = d_CAT[b * NCAT + lane];
        int sm  = d_SAMP[b * NCAT + lane];
        const float* oc = outp + NNUM + lane * KCLS;
        float v[KCLS];
        float mx = -1e30f;
        #pragma unroll
        for (int k = 0; k < KCLS; k++) { v[k] = oc[k]; mx = fmaxf(mx, v[k]); }
        float se = 0.f;
        #pragma unroll
        for (int k = 0; k < KCLS; k++) se += expf(v[k] - mx);
        float lse = mx + logf(se);

        float PH = laddexp(d_LOG_A[t], d_LOG_1M_A[t] - LOGK_F);
        float PO = laddexp(CL_F + d_LOG_A[t], d_LOG_1M_A[t] - LOGK_F);
        float H1, O1;
        if (t == 0) { H1 = 0.f; O1 = CL_F; }
        else {
            H1 = laddexp(d_LOG_CA[tm1], d_LOG_1M_CA[tm1] - LOGK_F);
            O1 = laddexp(CL_F + d_LOG_CA[tm1], d_LOG_1M_CA[tm1] - LOGK_F);
        }

        float unm[KCLS], unt[KCLS];
        float mmax = -1e30f, tmax = -1e30f;
        #pragma unroll
        for (int k = 0; k < KCLS; k++) {
            float lx0 = v[k] - lse;
            float ev  = (t == 0) ? lx0
                                 : laddexp(lx0 + d_LOG_CA[tm1], d_LOG_1M_CA[tm1] - LOGK_F);
            float pk  = (k == sm) ? PH : PO;
            float um = ev + pk;            unm[k] = um; mmax = fmaxf(mmax, um);
            float ut = ((k == hot) ? H1 : O1) + pk; unt[k] = ut; tmax = fmaxf(tmax, ut);
        }
        float ms = 0.f, ts = 0.f;
        #pragma unroll
        for (int k = 0; k < KCLS; k++) { ms += expf(unm[k] - mmax); ts += expf(unt[k] - tmax); }
        float mlse = mmax + logf(ms), tlse = tmax + logf(ts);
        float EXPL = expf(CL_F);
        #pragma unroll
        for (int k = 0; k < KCLS; k++) {
            float lt = unt[k] - tlse, lm = unm[k] - mlse;
            kl  += expf(lt) * (lt - lm);
            dec -= ((k == hot) ? 1.0f : EXPL) * lm;
        }
    }

    #pragma unroll
    for (int o = 16; o; o >>= 1) {
        g   += __shfl_xor_sync(0xffffffffu, g, o);
        kl  += __shfl_xor_sync(0xffffffffu, kl, o);
        dec += __shfl_xor_sync(0xffffffffu, dec, o);
    }
    if (lane == 0) {
        float Lt = (t == 0) ? dec : kl;
        s_row[warp] = (Lt + d_KLP) * (1.0f / ((float)NCAT * (float)BATCH))
                    + g * (1.0f / ((float)NNUM * (float)BATCH));
    }
    __syncthreads();
    if (threadIdx.x == 0) {
        float s = 0.f;
        #pragma unroll
        for (int i = 0; i < 8; i++) s += s_row[i];
        d_PART[blockIdx.x] = s;
    }
}

__global__ void final_kernel(float* __restrict__ out) {
    __shared__ float s[256];
    float a = 0.f;
    for (int i = threadIdx.x; i < BATCH / 8; i += 256) a += d_PART[i];
    s[threadIdx.x] = a;
    __syncthreads();
    for (int st = 128; st; st >>= 1) {
        if (threadIdx.x < st) s[threadIdx.x] += s[threadIdx.x + st];
        __syncthreads();
    }
    if (threadIdx.x == 0) out[0] = s[0];
}

// ---------------- launch ----------------
extern "C" void kernel_launch(void* const* d_in, const int* in_sizes, int n_in,
                              void* d_out, int out_size) {
    const float* x_num   = (const float*)d_in[0];
    const int*   x_cat_r = (const int*)  d_in[1];
    const int*   t_r     = (const int*)  d_in[2];
    const float* noise   = (const float*)d_in[3];
    const float* gumbel  = (const float*)d_in[4];
    const float* te_w1   = (const float*)d_in[5];
    const float* te_b1   = (const float*)d_in[6];
    const float* te_w2   = (const float*)d_in[7];
    const float* te_b2   = (const float*)d_in[8];
    const float* proj_w  = (const float*)d_in[9];
    const float* proj_b  = (const float*)d_in[10];
    const float* mlp_w1  = (const float*)d_in[11];
    const float* mlp_b1  = (const float*)d_in[12];
    const float* mlp_w2  = (const float*)d_in[13];
    const float* mlp_b2  = (const float*)d_in[14];
    float* out = (float*)d_out;

    cudaFuncSetAttribute(mma_gemm, cudaFuncAttributeMaxDynamicSharedMemorySize, GSMEM_BYTES);

    __nv_bfloat16 *pE0H, *pE0L, *pE1H, *pE1L;
    __nv_bfloat16 *pW1H, *pW1L, *pW2H, *pW2L, *pM1H, *pM1L, *pM2H, *pM2L, *pPJH, *pPJL;
    __nv_bfloat16 *pXIH, *pXIL, *pHH, *pHL, *pUH, *pUL;
    float *pEMB, *pOUT, *pB2;
    cudaGetSymbolAddress((void**)&pE0H, d_E0H); cudaGetSymbolAddress((void**)&pE0L, d_E0L);
    cudaGetSymbolAddress((void**)&pE1H, d_E1H); cudaGetSymbolAddress((void**)&pE1L, d_E1L);
    cudaGetSymbolAddress((void**)&pW1H, d_W1TH); cudaGetSymbolAddress((void**)&pW1L, d_W1TL);
    cudaGetSymbolAddress((void**)&pW2H, d_W2TH); cudaGetSymbolAddress((void**)&pW2L, d_W2TL);
    cudaGetSymbolAddress((void**)&pM1H, d_M1TH); cudaGetSymbolAddress((void**)&pM1L, d_M1TL);
    cudaGetSymbolAddress((void**)&pM2H, d_M2TH); cudaGetSymbolAddress((void**)&pM2L, d_M2TL);
    cudaGetSymbolAddress((void**)&pPJH, d_PJTH); cudaGetSymbolAddress((void**)&pPJL, d_PJTL);
    cudaGetSymbolAddress((void**)&pXIH, d_XINH); cudaGetSymbolAddress((void**)&pXIL, d_XINL);
    cudaGetSymbolAddress((void**)&pHH, d_HH); cudaGetSymbolAddress((void**)&pHL, d_HL);
    cudaGetSymbolAddress((void**)&pUH, d_UH); cudaGetSymbolAddress((void**)&pUL, d_UL);
    cudaGetSymbolAddress((void**)&pEMB, d_EMB); cudaGetSymbolAddress((void**)&pOUT, d_OUT);
    cudaGetSymbolAddress((void**)&pB2, d_B2P);

    sched_kernel<<<1, 1024>>>();                                            // 0
    detect_kernel<<<1, 32>>>(t_r, x_cat_r);                                 // 1
    convert_all_kernel<<<(BATCH * NCAT + 255) / 256, 256>>>(t_r, x_cat_r, mlp_b2); // 2
    temb_kernel<<<dim3(TPAD, DIMT / 256), 256>>>();                         // 3
    transpose_all_kernel<<<4096, dim3(32, 8)>>>(te_w1, te_w2, mlp_w1, mlp_w2, proj_w); // 4

    // te MLP over 1024 (padded) unique timesteps        (launch 5 -> ncu target)
    mma_gemm<<<dim3(DIMT / 128, TPAD / 128), 256, GSMEM_BYTES>>>(
        pE0H, pE0L, pW1H, pW1L, te_b1, nullptr, pE1H, pE1L, nullptr, DIMT, DIMT, /*silu*/2);
    mma_gemm<<<dim3(DIMT / 128, TPAD / 128), 256, GSMEM_BYTES>>>(
        pE1H, pE1L, pW2H, pW2L, te_b2, pEMB, nullptr, nullptr, nullptr, DIMT, DIMT, /*fp32*/0);

    build_xin_kernel<<<BATCH, 128>>>(x_num, noise, gumbel);

    // proj: h = x_in@proj_w + proj_b + emb[t]   -> hi/lo
    mma_gemm<<<dim3(DIMT / 128, BATCH / 128), 256, GSMEM_BYTES>>>(
        pXIH, pXIL, pPJH, pPJL, proj_b, nullptr, pHH, pHL, pEMB, KPAD, DIMT, /*emb*/3);
    // mlp1: relu -> hi/lo
    mma_gemm<<<dim3(HIDN / 128, BATCH / 128), 256, GSMEM_BYTES>>>(
        pHH, pHL, pM1H, pM1L, mlp_b1, nullptr, pUH, pUL, nullptr, DIMT, HIDN, /*relu*/1);
    // mlp2: fp32 out (padded to 512)
    mma_gemm<<<dim3(NPAD2 / 128, BATCH / 128), 256, GSMEM_BYTES>>>(
        pUH, pUL, pM2H, pM2L, pB2, pOUT, nullptr, nullptr, nullptr, HIDN, NPAD2, /*fp32*/0);

    loss_kernel<<<BATCH / 8, 256>>>(noise);
    final_kernel<<<1, 256>>>(out);
}